// round 11
// baseline (speedup 1.0000x reference)
#include <cuda_runtime.h>
#include <cuda_bf16.h>
#include <math.h>

// Problem constants
#define NN      8000
#define NFEAT   512
#define NHID    128
#define NCLS    64
#define CAP     96
#define EPS     1e-12f

#define AST 20            // As smem stride (16 + 4 pad)
#define BST 136           // Bs smem stride (128 + 8 pad)

// ---------------- scratch (device globals; no allocation allowed) ------------
__device__ float g_h     [NN * NHID];
__device__ float g_li0   [NN * NHID];
__device__ float g_yhat  [NN * NCLS];
__device__ int   g_cols  [NN * CAP];
__device__ float g_w     [NN * CAP];
__device__ int   g_deg   [NN];
__device__ int   g_cnt   [NN];

// ---------------- helpers ----------------------------------------------------
__device__ __forceinline__ unsigned f2tf(float f) {
    unsigned u;
    asm("cvt.rna.tf32.f32 %0, %1;" : "=r"(u) : "f"(f));
    return u;
}

#define MMA_TF32(cc, a, b0_, b1_)                                              \
    asm volatile(                                                              \
        "mma.sync.aligned.m16n8k8.row.col.f32.tf32.tf32.f32 "                  \
        "{%0,%1,%2,%3}, {%4,%5,%6,%7}, {%8,%9}, {%0,%1,%2,%3};"                \
        : "+f"(cc[0]), "+f"(cc[1]), "+f"(cc[2]), "+f"(cc[3])                   \
        : "r"(a[0]), "r"(a[1]), "r"(a[2]), "r"(a[3]), "r"(b0_), "r"(b1_))

// =============================================================================
// KERNEL 1: GEMM1 (tensor tf32-split): h = relu(x @ W0 + b0)
// [R5 verbatim: BM=64 BN=128 BK=16, 128 threads, warp tile 32x64]
// =============================================================================
__global__ __launch_bounds__(128) void gemm1_tc(const float* __restrict__ x,
                                                const float* __restrict__ W0,
                                                const float* __restrict__ b0) {
    __shared__ unsigned Ah[64 * AST], Al[64 * AST];
    __shared__ unsigned Bh[16 * BST], Bl[16 * BST];

    const int tid  = threadIdx.x;
    const int warp = tid >> 5;
    const int lane = tid & 31;
    const int m0   = blockIdx.x * 64;
    const int wm   = (warp & 1) * 32;
    const int wn   = (warp >> 1) * 64;

    float c[2][8][4];
#pragma unroll
    for (int mt = 0; mt < 2; mt++)
#pragma unroll
        for (int nt = 0; nt < 8; nt++)
#pragma unroll
            for (int r = 0; r < 4; r++) c[mt][nt][r] = 0.0f;

    const int ra = tid >> 1, ca = (tid & 1) * 8;
    const int rb = tid >> 3, cb = (tid & 7) * 16;
    float4 xa[2], wb[4];

    {
        const float* xp = x + (size_t)(m0 + ra) * NFEAT + ca;
        xa[0] = *(const float4*)(xp);
        xa[1] = *(const float4*)(xp + 4);
        const float* wp = W0 + (size_t)rb * NHID + cb;
#pragma unroll
        for (int i = 0; i < 4; i++) wb[i] = *(const float4*)(wp + i * 4);
    }

    for (int it = 0; it < 32; it++) {
        {
            const float* av = (const float*)xa;
#pragma unroll
            for (int j = 0; j < 8; j++) {
                float v  = av[j];
                unsigned hb = f2tf(v);
                Ah[ra * AST + ca + j] = hb;
                Al[ra * AST + ca + j] = f2tf(v - __uint_as_float(hb));
            }
            const float* bv = (const float*)wb;
#pragma unroll
            for (int j = 0; j < 16; j++) {
                float v  = bv[j];
                unsigned hb = f2tf(v);
                Bh[rb * BST + cb + j] = hb;
                Bl[rb * BST + cb + j] = f2tf(v - __uint_as_float(hb));
            }
        }
        __syncthreads();

        if (it < 31) {
            int k0 = (it + 1) * 16;
            const float* xp = x + (size_t)(m0 + ra) * NFEAT + k0 + ca;
            xa[0] = *(const float4*)(xp);
            xa[1] = *(const float4*)(xp + 4);
            const float* wp = W0 + (size_t)(k0 + rb) * NHID + cb;
#pragma unroll
            for (int i = 0; i < 4; i++) wb[i] = *(const float4*)(wp + i * 4);
        }

#pragma unroll
        for (int ks = 0; ks < 16; ks += 8) {
            unsigned ah[2][4], al[2][4];
            const int arow = wm + (lane >> 2);
            const int ac   = ks + (lane & 3);
#pragma unroll
            for (int mt = 0; mt < 2; mt++) {
                int r = arow + mt * 16;
                ah[mt][0] = Ah[r * AST + ac];
                ah[mt][1] = Ah[(r + 8) * AST + ac];
                ah[mt][2] = Ah[r * AST + ac + 4];
                ah[mt][3] = Ah[(r + 8) * AST + ac + 4];
                al[mt][0] = Al[r * AST + ac];
                al[mt][1] = Al[(r + 8) * AST + ac];
                al[mt][2] = Al[r * AST + ac + 4];
                al[mt][3] = Al[(r + 8) * AST + ac + 4];
            }
#pragma unroll
            for (int nt = 0; nt < 8; nt++) {
                const int bn = wn + nt * 8 + (lane >> 2);
                const int bk = ks + (lane & 3);
                unsigned bh0 = Bh[bk * BST + bn];
                unsigned bh1 = Bh[(bk + 4) * BST + bn];
                unsigned bl0 = Bl[bk * BST + bn];
                unsigned bl1 = Bl[(bk + 4) * BST + bn];
#pragma unroll
                for (int mt = 0; mt < 2; mt++) {
                    MMA_TF32(c[mt][nt], ah[mt], bh0, bh1);
                    MMA_TF32(c[mt][nt], ah[mt], bl0, bl1);
                    MMA_TF32(c[mt][nt], al[mt], bh0, bh1);
                }
            }
        }
        __syncthreads();
    }

#pragma unroll
    for (int nt = 0; nt < 8; nt++) {
        int col = wn + nt * 8 + 2 * (lane & 3);
        float bias0 = b0[col], bias1 = b0[col + 1];
#pragma unroll
        for (int mt = 0; mt < 2; mt++) {
            int r = m0 + wm + mt * 16 + (lane >> 2);
            g_h[(size_t)r * NHID + col]           = fmaxf(c[mt][nt][0] + bias0, 0.0f);
            g_h[(size_t)r * NHID + col + 1]       = fmaxf(c[mt][nt][1] + bias1, 0.0f);
            g_h[(size_t)(r + 8) * NHID + col]     = fmaxf(c[mt][nt][2] + bias0, 0.0f);
            g_h[(size_t)(r + 8) * NHID + col + 1] = fmaxf(c[mt][nt][3] + bias1, 0.0f);
        }
    }
}

// =============================================================================
// KERNEL cnt: train-index multiplicity histogram (tiny)
// =============================================================================
__global__ void cnt_kernel(const int* __restrict__ idx_tr) {
    int t = threadIdx.x;
    for (int i = t; i < NN; i += 256) g_cnt[i] = 0;
    __syncthreads();
    if (t < 250) {
        atomicAdd(&g_cnt[idx_tr[t]], 1);
        atomicAdd(&g_cnt[idx_tr[t + 250]], 1);
    }
}

// =============================================================================
// KERNEL 2: adjacency extraction (1 warp/row), ballot fast-path for empty chunks
// =============================================================================
__global__ __launch_bounds__(256) void extract_adj_kernel(const float* __restrict__ adj) {
    int row_id = blockIdx.x * 8 + (threadIdx.x >> 5);
    int lane = threadIdx.x & 31;
    const float* row = adj + (size_t)row_id * NN;
    int base = 0;
    for (int c0 = 0; c0 < 7936; c0 += 128) {
        float4 v = *(const float4*)(row + c0 + lane * 4);
        unsigned m4 = (v.x != 0.0f) | ((v.y != 0.0f) << 1) |
                      ((v.z != 0.0f) << 2) | ((v.w != 0.0f) << 3);
        unsigned act = __ballot_sync(0xffffffffu, m4 != 0);
        if (act == 0) continue;
        int nz = __popc(m4);
        while (act) {
            int l   = __ffs(act) - 1;
            int c_l = __shfl_sync(0xffffffffu, nz, l);
            if (lane == l) {
                int p = base;
                int col = c0 + lane * 4;
                if (m4 & 1) { if (p < CAP) g_cols[row_id * CAP + p] = col;     p++; }
                if (m4 & 2) { if (p < CAP) g_cols[row_id * CAP + p] = col + 1; p++; }
                if (m4 & 4) { if (p < CAP) g_cols[row_id * CAP + p] = col + 2; p++; }
                if (m4 & 8) { if (p < CAP) g_cols[row_id * CAP + p] = col + 3; }
            }
            base += c_l;
            act &= act - 1;
        }
    }
    {
        float2 v = *(const float2*)(row + 7936 + lane * 2);
        unsigned m2 = (v.x != 0.0f) | ((v.y != 0.0f) << 1);
        unsigned act = __ballot_sync(0xffffffffu, m2 != 0);
        int nz = __popc(m2);
        while (act) {
            int l   = __ffs(act) - 1;
            int c_l = __shfl_sync(0xffffffffu, nz, l);
            if (lane == l) {
                int p = base;
                int col = 7936 + lane * 2;
                if (m2 & 1) { if (p < CAP) g_cols[row_id * CAP + p] = col;     p++; }
                if (m2 & 2) { if (p < CAP) g_cols[row_id * CAP + p] = col + 1; }
            }
            base += c_l;
            act &= act - 1;
        }
    }
    if (lane == 0) g_deg[row_id] = base < CAP ? base : CAP;
}

// =============================================================================
// KERNEL 3: Pseudo = h@W1 + b1 + 0.1*cnt*y_label; emit; yhat = softmax
// =============================================================================
__global__ void pseudo_fused(const float* __restrict__ W1,
                             const float* __restrict__ b1,
                             const float* __restrict__ y_label,
                             float* __restrict__ out_pseudo) {
    int ry = threadIdx.y, c = threadIdx.x;
    int row = blockIdx.x * 4 + ry;
    __shared__ float hr[4][128];
    hr[ry][c]      = g_h[(size_t)row * NHID + c];
    hr[ry][c + 64] = g_h[(size_t)row * NHID + c + 64];
    __syncthreads();
    float acc = b1[c];
#pragma unroll 8
    for (int k = 0; k < NHID; k++) acc += hr[ry][k] * W1[k * NCLS + c];

    int cnt = g_cnt[row];
    if (cnt) acc += 0.1f * (float)cnt * y_label[(size_t)row * NCLS + c];

    out_pseudo[(size_t)row * NCLS + c] = acc;

    __shared__ float sm[4][2];
    int wu = c >> 5, lane = c & 31;
    float m = acc;
#pragma unroll
    for (int o = 16; o; o >>= 1) m = fmaxf(m, __shfl_xor_sync(0xffffffffu, m, o));
    if (lane == 0) sm[ry][wu] = m;
    __syncthreads();
    m = fmaxf(sm[ry][0], sm[ry][1]);
    __syncthreads();
    float e = expf(acc - m);
    float s = e;
#pragma unroll
    for (int o = 16; o; o >>= 1) s += __shfl_xor_sync(0xffffffffu, s, o);
    if (lane == 0) sm[ry][wu] = s;
    __syncthreads();
    s = sm[ry][0] + sm[ry][1];
    g_yhat[(size_t)row * NCLS + c] = e / s;
}

// =============================================================================
// KERNEL 4: edge weights + propagation layer 0
// [R7 verbatim: serial ssum at t==0 — implicated shuffle version REVERTED]
// =============================================================================
__global__ __launch_bounds__(128) void ew_prop0() {
    int row = blockIdx.x;
    __shared__ float yi[NCLS];
    __shared__ int   cs[CAP];
    __shared__ float ws[CAP];
    __shared__ float w4[4];
    __shared__ float ssum;
    int t = threadIdx.x;
    int wid = t >> 5, lane = t & 31;
    int deg = g_deg[row];
    if (t < NCLS) yi[t] = g_yhat[(size_t)row * NCLS + t];
    if (t < deg)  cs[t] = g_cols[row * CAP + t];
    __syncthreads();

    for (int n = wid; n < deg; n += 4) {
        const float* yj = g_yhat + (size_t)cs[n] * NCLS;
        float p = yi[lane] * yj[lane] + yi[lane + 32] * yj[lane + 32];
#pragma unroll
        for (int o = 16; o; o >>= 1) p += __shfl_down_sync(0xffffffffu, p, o);
        if (lane == 0) ws[n] = p;
    }
    __syncthreads();
    if (t == 0) {
        float s = 0.0f;
        for (int n = 0; n < deg; n++) s += ws[n];
        ssum = fmaxf(s, EPS);
    }
    __syncthreads();
    if (t < deg) {
        float wn = ws[t] / ssum;
        ws[t] = wn;
        g_w[row * CAP + t] = wn;
    }
    __syncthreads();

    // SpMM, 4x unrolled with independent loads (MLP=4)
    float s = 0.0f;
    int n = 0;
    for (; n + 4 <= deg; n += 4) {
        float a0 = g_h[(size_t)cs[n]     * NHID + t];
        float a1 = g_h[(size_t)cs[n + 1] * NHID + t];
        float a2 = g_h[(size_t)cs[n + 2] * NHID + t];
        float a3 = g_h[(size_t)cs[n + 3] * NHID + t];
        s += ws[n] * a0 + ws[n + 1] * a1 + ws[n + 2] * a2 + ws[n + 3] * a3;
    }
    for (; n < deg; n++) s += ws[n] * g_h[(size_t)cs[n] * NHID + t];

    float v = 0.9f * s + 0.1f * g_h[(size_t)row * NHID + t];

    float q = v * v;
#pragma unroll
    for (int o = 16; o; o >>= 1) q += __shfl_xor_sync(0xffffffffu, q, o);
    if (lane == 0) w4[wid] = q;
    __syncthreads();
    float nrm = fmaxf(sqrtf(w4[0] + w4[1] + w4[2] + w4[3]), EPS);
    g_li0[(size_t)row * NHID + t] = v / nrm;
}

// =============================================================================
// KERNEL 5: propagation layer 1 + log_softmax(li1 @ W2 + b2)
// =============================================================================
__global__ __launch_bounds__(128) void prop1_final(const float* __restrict__ W2,
                                                   const float* __restrict__ b2,
                                                   float* __restrict__ out) {
    int row = blockIdx.x;
    __shared__ int   cs[CAP];
    __shared__ float ws[CAP];
    __shared__ float li[NHID];
    __shared__ float pacc[NHID];
    __shared__ float w4[4];
    __shared__ float sm[4];
    int t = threadIdx.x;
    int wid = t >> 5, lane = t & 31;
    int deg = g_deg[row];
    if (t < deg) { cs[t] = g_cols[row * CAP + t]; ws[t] = g_w[row * CAP + t]; }
    __syncthreads();

    float s = 0.0f;
    int n = 0;
    for (; n + 4 <= deg; n += 4) {
        float a0 = g_li0[(size_t)cs[n]     * NHID + t];
        float a1 = g_li0[(size_t)cs[n + 1] * NHID + t];
        float a2 = g_li0[(size_t)cs[n + 2] * NHID + t];
        float a3 = g_li0[(size_t)cs[n + 3] * NHID + t];
        s += ws[n] * a0 + ws[n + 1] * a1 + ws[n + 2] * a2 + ws[n + 3] * a3;
    }
    for (; n < deg; n++) s += ws[n] * g_li0[(size_t)cs[n] * NHID + t];

    float v = 0.9f * s + 0.1f * g_h[(size_t)row * NHID + t];

    float q = v * v;
#pragma unroll
    for (int o = 16; o; o >>= 1) q += __shfl_xor_sync(0xffffffffu, q, o);
    if (lane == 0) w4[wid] = q;
    __syncthreads();
    float nrm = fmaxf(sqrtf(w4[0] + w4[1] + w4[2] + w4[3]), EPS);
    li[t] = v / nrm;
    __syncthreads();

    int c = t & 63, ph = t >> 6;
    float a = 0.0f;
#pragma unroll 8
    for (int k = ph * 64; k < ph * 64 + 64; k++) a += li[k] * W2[k * NCLS + c];
    pacc[t] = a;
    __syncthreads();

    float acc = pacc[c] + pacc[64 + c] + b2[c];

    float m = acc;
#pragma unroll
    for (int o = 16; o; o >>= 1) m = fmaxf(m, __shfl_xor_sync(0xffffffffu, m, o));
    if (lane == 0) sm[wid] = m;
    __syncthreads();
    m = fmaxf(sm[0], sm[1]);
    __syncthreads();
    float sh = acc - m;
    float e = expf(sh);
    float ss = e;
#pragma unroll
    for (int o = 16; o; o >>= 1) ss += __shfl_xor_sync(0xffffffffu, ss, o);
    if (lane == 0) sm[wid] = ss;
    __syncthreads();
    ss = sm[0] + sm[1];
    if (t < 64) out[(size_t)row * NCLS + c] = sh - logf(ss);
}

// ---------------- launch: 2-stream fork/join inside the captured graph --------
extern "C" void kernel_launch(void* const* d_in, const int* in_sizes, int n_in,
                              void* d_out, int out_size) {
    const float* x      = (const float*)d_in[0];
    const float* adj    = (const float*)d_in[1];
    const float* y_lab  = (const float*)d_in[2];
    const int*   idx_tr = (const int*)  d_in[3];
    const float* W0     = (const float*)d_in[4];
    const float* b0     = (const float*)d_in[5];
    const float* W1     = (const float*)d_in[6];
    const float* b1     = (const float*)d_in[7];
    const float* W2     = (const float*)d_in[8];
    const float* b2     = (const float*)d_in[9];
    float* out = (float*)d_out;

    static cudaStream_t s2 = nullptr;
    static cudaEvent_t evFork = nullptr, evCnt = nullptr, evExt = nullptr;
    if (s2 == nullptr) {
        cudaStreamCreateWithFlags(&s2, cudaStreamNonBlocking);
        cudaEventCreateWithFlags(&evFork, cudaEventDisableTiming);
        cudaEventCreateWithFlags(&evCnt,  cudaEventDisableTiming);
        cudaEventCreateWithFlags(&evExt,  cudaEventDisableTiming);
    }

    cudaEventRecord(evFork, 0);
    cudaStreamWaitEvent(s2, evFork, 0);

    cnt_kernel<<<1, 256, 0, s2>>>(idx_tr);
    cudaEventRecord(evCnt, s2);
    extract_adj_kernel<<<1000, 256, 0, s2>>>(adj);
    cudaEventRecord(evExt, s2);

    gemm1_tc<<<NN / 64, 128>>>(x, W0, b0);                       // stream 0
    cudaStreamWaitEvent(0, evCnt, 0);
    pseudo_fused<<<NN / 4, dim3(64, 4)>>>(W1, b1, y_lab, out + (size_t)NN * NCLS);
    cudaStreamWaitEvent(0, evExt, 0);
    ew_prop0<<<NN, 128>>>();
    prop1_final<<<NN, 128>>>(W2, b2, out);
}

// round 12
// speedup vs baseline: 1.0060x; 1.0060x over previous
#include <cuda_runtime.h>
#include <cuda_bf16.h>
#include <math.h>

// Problem constants
#define NN      8000
#define NFEAT   512
#define NHID    128
#define NCLS    64
#define CAP     96
#define EPS     1e-12f
#define NTRAIN  500

#define AST 20            // As smem stride (16 + 4 pad)
#define BST 136           // Bs smem stride (128 + 8 pad)

// ---------------- scratch (device globals; no allocation allowed) ------------
__device__ float g_h     [NN * NHID];
__device__ float g_li0   [NN * NHID];
__device__ float g_yhat  [NN * NCLS];
__device__ int   g_cols  [NN * CAP];
__device__ float g_w     [NN * CAP];
__device__ int   g_deg   [NN];

// ---------------- helpers ----------------------------------------------------
__device__ __forceinline__ unsigned f2tf(float f) {
    unsigned u;
    asm("cvt.rna.tf32.f32 %0, %1;" : "=r"(u) : "f"(f));
    return u;
}

#define MMA_TF32(cc, a, b0_, b1_)                                              \
    asm volatile(                                                              \
        "mma.sync.aligned.m16n8k8.row.col.f32.tf32.tf32.f32 "                  \
        "{%0,%1,%2,%3}, {%4,%5,%6,%7}, {%8,%9}, {%0,%1,%2,%3};"                \
        : "+f"(cc[0]), "+f"(cc[1]), "+f"(cc[2]), "+f"(cc[3])                   \
        : "r"(a[0]), "r"(a[1]), "r"(a[2]), "r"(a[3]), "r"(b0_), "r"(b1_))

// =============================================================================
// KERNEL 1: GEMM1 (tensor tf32-split): h = relu(x @ W0 + b0)   [champion verbatim]
// =============================================================================
__global__ __launch_bounds__(128) void gemm1_tc(const float* __restrict__ x,
                                                const float* __restrict__ W0,
                                                const float* __restrict__ b0) {
    __shared__ unsigned Ah[64 * AST], Al[64 * AST];
    __shared__ unsigned Bh[16 * BST], Bl[16 * BST];

    const int tid  = threadIdx.x;
    const int warp = tid >> 5;
    const int lane = tid & 31;
    const int m0   = blockIdx.x * 64;
    const int wm   = (warp & 1) * 32;
    const int wn   = (warp >> 1) * 64;

    float c[2][8][4];
#pragma unroll
    for (int mt = 0; mt < 2; mt++)
#pragma unroll
        for (int nt = 0; nt < 8; nt++)
#pragma unroll
            for (int r = 0; r < 4; r++) c[mt][nt][r] = 0.0f;

    const int ra = tid >> 1, ca = (tid & 1) * 8;
    const int rb = tid >> 3, cb = (tid & 7) * 16;
    float4 xa[2], wb[4];

    {
        const float* xp = x + (size_t)(m0 + ra) * NFEAT + ca;
        xa[0] = *(const float4*)(xp);
        xa[1] = *(const float4*)(xp + 4);
        const float* wp = W0 + (size_t)rb * NHID + cb;
#pragma unroll
        for (int i = 0; i < 4; i++) wb[i] = *(const float4*)(wp + i * 4);
    }

    for (int it = 0; it < 32; it++) {
        {
            const float* av = (const float*)xa;
#pragma unroll
            for (int j = 0; j < 8; j++) {
                float v  = av[j];
                unsigned hb = f2tf(v);
                Ah[ra * AST + ca + j] = hb;
                Al[ra * AST + ca + j] = f2tf(v - __uint_as_float(hb));
            }
            const float* bv = (const float*)wb;
#pragma unroll
            for (int j = 0; j < 16; j++) {
                float v  = bv[j];
                unsigned hb = f2tf(v);
                Bh[rb * BST + cb + j] = hb;
                Bl[rb * BST + cb + j] = f2tf(v - __uint_as_float(hb));
            }
        }
        __syncthreads();

        if (it < 31) {
            int k0 = (it + 1) * 16;
            const float* xp = x + (size_t)(m0 + ra) * NFEAT + k0 + ca;
            xa[0] = *(const float4*)(xp);
            xa[1] = *(const float4*)(xp + 4);
            const float* wp = W0 + (size_t)(k0 + rb) * NHID + cb;
#pragma unroll
            for (int i = 0; i < 4; i++) wb[i] = *(const float4*)(wp + i * 4);
        }

#pragma unroll
        for (int ks = 0; ks < 16; ks += 8) {
            unsigned ah[2][4], al[2][4];
            const int arow = wm + (lane >> 2);
            const int ac   = ks + (lane & 3);
#pragma unroll
            for (int mt = 0; mt < 2; mt++) {
                int r = arow + mt * 16;
                ah[mt][0] = Ah[r * AST + ac];
                ah[mt][1] = Ah[(r + 8) * AST + ac];
                ah[mt][2] = Ah[r * AST + ac + 4];
                ah[mt][3] = Ah[(r + 8) * AST + ac + 4];
                al[mt][0] = Al[r * AST + ac];
                al[mt][1] = Al[(r + 8) * AST + ac];
                al[mt][2] = Al[r * AST + ac + 4];
                al[mt][3] = Al[(r + 8) * AST + ac + 4];
            }
#pragma unroll
            for (int nt = 0; nt < 8; nt++) {
                const int bn = wn + nt * 8 + (lane >> 2);
                const int bk = ks + (lane & 3);
                unsigned bh0 = Bh[bk * BST + bn];
                unsigned bh1 = Bh[(bk + 4) * BST + bn];
                unsigned bl0 = Bl[bk * BST + bn];
                unsigned bl1 = Bl[(bk + 4) * BST + bn];
#pragma unroll
                for (int mt = 0; mt < 2; mt++) {
                    MMA_TF32(c[mt][nt], ah[mt], bh0, bh1);
                    MMA_TF32(c[mt][nt], ah[mt], bl0, bl1);
                    MMA_TF32(c[mt][nt], al[mt], bh0, bh1);
                }
            }
        }
        __syncthreads();
    }

#pragma unroll
    for (int nt = 0; nt < 8; nt++) {
        int col = wn + nt * 8 + 2 * (lane & 3);
        float bias0 = b0[col], bias1 = b0[col + 1];
#pragma unroll
        for (int mt = 0; mt < 2; mt++) {
            int r = m0 + wm + mt * 16 + (lane >> 2);
            g_h[(size_t)r * NHID + col]           = fmaxf(c[mt][nt][0] + bias0, 0.0f);
            g_h[(size_t)r * NHID + col + 1]       = fmaxf(c[mt][nt][1] + bias1, 0.0f);
            g_h[(size_t)(r + 8) * NHID + col]     = fmaxf(c[mt][nt][2] + bias0, 0.0f);
            g_h[(size_t)(r + 8) * NHID + col + 1] = fmaxf(c[mt][nt][3] + bias1, 0.0f);
        }
    }
}

// =============================================================================
// KERNEL 2: adjacency extraction (1 warp/row)   [champion verbatim]
// =============================================================================
__global__ __launch_bounds__(256) void extract_adj_kernel(const float* __restrict__ adj) {
    int row_id = blockIdx.x * 8 + (threadIdx.x >> 5);
    int lane = threadIdx.x & 31;
    const float* row = adj + (size_t)row_id * NN;
    int base = 0;
    for (int c0 = 0; c0 < 7936; c0 += 128) {
        float4 v = *(const float4*)(row + c0 + lane * 4);
        unsigned m4 = (v.x != 0.0f) | ((v.y != 0.0f) << 1) |
                      ((v.z != 0.0f) << 2) | ((v.w != 0.0f) << 3);
        unsigned act = __ballot_sync(0xffffffffu, m4 != 0);
        if (act == 0) continue;
        int nz = __popc(m4);
        while (act) {
            int l   = __ffs(act) - 1;
            int c_l = __shfl_sync(0xffffffffu, nz, l);
            if (lane == l) {
                int p = base;
                int col = c0 + lane * 4;
                if (m4 & 1) { if (p < CAP) g_cols[row_id * CAP + p] = col;     p++; }
                if (m4 & 2) { if (p < CAP) g_cols[row_id * CAP + p] = col + 1; p++; }
                if (m4 & 4) { if (p < CAP) g_cols[row_id * CAP + p] = col + 2; p++; }
                if (m4 & 8) { if (p < CAP) g_cols[row_id * CAP + p] = col + 3; }
            }
            base += c_l;
            act &= act - 1;
        }
    }
    {
        float2 v = *(const float2*)(row + 7936 + lane * 2);
        unsigned m2 = (v.x != 0.0f) | ((v.y != 0.0f) << 1);
        unsigned act = __ballot_sync(0xffffffffu, m2 != 0);
        int nz = __popc(m2);
        while (act) {
            int l   = __ffs(act) - 1;
            int c_l = __shfl_sync(0xffffffffu, nz, l);
            if (lane == l) {
                int p = base;
                int col = 7936 + lane * 2;
                if (m2 & 1) { if (p < CAP) g_cols[row_id * CAP + p] = col;     p++; }
                if (m2 & 2) { if (p < CAP) g_cols[row_id * CAP + p] = col + 1; }
            }
            base += c_l;
            act &= act - 1;
        }
    }
    if (lane == 0) g_deg[row_id] = base < CAP ? base : CAP;
}

// =============================================================================
// KERNEL 3: Pseudo = h@W1 + b1 + 0.1*cnt*y_label; emit; yhat = softmax
// [ONLY change this round: cnt computed in-kernel from smem-resident idx_tr,
//  removing the cnt_kernel node and its event pair from the graph]
// =============================================================================
__global__ void pseudo_fused(const float* __restrict__ W1,
                             const float* __restrict__ b1,
                             const float* __restrict__ y_label,
                             const int*   __restrict__ idx_tr,
                             float* __restrict__ out_pseudo) {
    int ry = threadIdx.y, c = threadIdx.x;
    int row = blockIdx.x * 4 + ry;
    int tid = ry * 64 + c;
    __shared__ float hr[4][128];
    __shared__ int   idxs[NTRAIN];
    __shared__ float sm[4][2];
    __shared__ int   scnt[4][2];

    hr[ry][c]      = g_h[(size_t)row * NHID + c];
    hr[ry][c + 64] = g_h[(size_t)row * NHID + c + 64];
    for (int i = tid; i < NTRAIN; i += 256) idxs[i] = idx_tr[i];
    __syncthreads();

    float acc = b1[c];
#pragma unroll 8
    for (int k = 0; k < NHID; k++) acc += hr[ry][k] * W1[k * NCLS + c];

    // multiplicity of `row` in idx_train (exact, deterministic)
    int wu = c >> 5, lane = c & 31;
    int cnt = 0;
    for (int i = c; i < NTRAIN; i += 64) cnt += (idxs[i] == row);
#pragma unroll
    for (int o = 16; o; o >>= 1) cnt += __shfl_xor_sync(0xffffffffu, cnt, o);
    if (lane == 0) scnt[ry][wu] = cnt;
    __syncthreads();
    cnt = scnt[ry][0] + scnt[ry][1];
    if (cnt) acc += 0.1f * (float)cnt * y_label[(size_t)row * NCLS + c];

    out_pseudo[(size_t)row * NCLS + c] = acc;

    float m = acc;
#pragma unroll
    for (int o = 16; o; o >>= 1) m = fmaxf(m, __shfl_xor_sync(0xffffffffu, m, o));
    if (lane == 0) sm[ry][wu] = m;
    __syncthreads();
    m = fmaxf(sm[ry][0], sm[ry][1]);
    __syncthreads();
    float e = expf(acc - m);
    float s = e;
#pragma unroll
    for (int o = 16; o; o >>= 1) s += __shfl_xor_sync(0xffffffffu, s, o);
    if (lane == 0) sm[ry][wu] = s;
    __syncthreads();
    s = sm[ry][0] + sm[ry][1];
    g_yhat[(size_t)row * NCLS + c] = e / s;
}

// =============================================================================
// KERNEL 4: edge weights + propagation layer 0   [champion verbatim]
// =============================================================================
__global__ __launch_bounds__(128) void ew_prop0() {
    int row = blockIdx.x;
    __shared__ float yi[NCLS];
    __shared__ int   cs[CAP];
    __shared__ float ws[CAP];
    __shared__ float w4[4];
    __shared__ float ssum;
    int t = threadIdx.x;
    int wid = t >> 5, lane = t & 31;
    int deg = g_deg[row];
    if (t < NCLS) yi[t] = g_yhat[(size_t)row * NCLS + t];
    if (t < deg)  cs[t] = g_cols[row * CAP + t];
    __syncthreads();

    for (int n = wid; n < deg; n += 4) {
        const float* yj = g_yhat + (size_t)cs[n] * NCLS;
        float p = yi[lane] * yj[lane] + yi[lane + 32] * yj[lane + 32];
#pragma unroll
        for (int o = 16; o; o >>= 1) p += __shfl_down_sync(0xffffffffu, p, o);
        if (lane == 0) ws[n] = p;
    }
    __syncthreads();
    if (t == 0) {
        float s = 0.0f;
        for (int n = 0; n < deg; n++) s += ws[n];
        ssum = fmaxf(s, EPS);
    }
    __syncthreads();
    if (t < deg) {
        float wn = ws[t] / ssum;
        ws[t] = wn;
        g_w[row * CAP + t] = wn;
    }
    __syncthreads();

    float s = 0.0f;
    int n = 0;
    for (; n + 4 <= deg; n += 4) {
        float a0 = g_h[(size_t)cs[n]     * NHID + t];
        float a1 = g_h[(size_t)cs[n + 1] * NHID + t];
        float a2 = g_h[(size_t)cs[n + 2] * NHID + t];
        float a3 = g_h[(size_t)cs[n + 3] * NHID + t];
        s += ws[n] * a0 + ws[n + 1] * a1 + ws[n + 2] * a2 + ws[n + 3] * a3;
    }
    for (; n < deg; n++) s += ws[n] * g_h[(size_t)cs[n] * NHID + t];

    float v = 0.9f * s + 0.1f * g_h[(size_t)row * NHID + t];

    float q = v * v;
#pragma unroll
    for (int o = 16; o; o >>= 1) q += __shfl_xor_sync(0xffffffffu, q, o);
    if (lane == 0) w4[wid] = q;
    __syncthreads();
    float nrm = fmaxf(sqrtf(w4[0] + w4[1] + w4[2] + w4[3]), EPS);
    g_li0[(size_t)row * NHID + t] = v / nrm;
}

// =============================================================================
// KERNEL 5: propagation layer 1 + log_softmax(li1 @ W2 + b2)   [champion verbatim]
// =============================================================================
__global__ __launch_bounds__(128) void prop1_final(const float* __restrict__ W2,
                                                   const float* __restrict__ b2,
                                                   float* __restrict__ out) {
    int row = blockIdx.x;
    __shared__ int   cs[CAP];
    __shared__ float ws[CAP];
    __shared__ float li[NHID];
    __shared__ float pacc[NHID];
    __shared__ float w4[4];
    __shared__ float sm[4];
    int t = threadIdx.x;
    int wid = t >> 5, lane = t & 31;
    int deg = g_deg[row];
    if (t < deg) { cs[t] = g_cols[row * CAP + t]; ws[t] = g_w[row * CAP + t]; }
    __syncthreads();

    float s = 0.0f;
    int n = 0;
    for (; n + 4 <= deg; n += 4) {
        float a0 = g_li0[(size_t)cs[n]     * NHID + t];
        float a1 = g_li0[(size_t)cs[n + 1] * NHID + t];
        float a2 = g_li0[(size_t)cs[n + 2] * NHID + t];
        float a3 = g_li0[(size_t)cs[n + 3] * NHID + t];
        s += ws[n] * a0 + ws[n + 1] * a1 + ws[n + 2] * a2 + ws[n + 3] * a3;
    }
    for (; n < deg; n++) s += ws[n] * g_li0[(size_t)cs[n] * NHID + t];

    float v = 0.9f * s + 0.1f * g_h[(size_t)row * NHID + t];

    float q = v * v;
#pragma unroll
    for (int o = 16; o; o >>= 1) q += __shfl_xor_sync(0xffffffffu, q, o);
    if (lane == 0) w4[wid] = q;
    __syncthreads();
    float nrm = fmaxf(sqrtf(w4[0] + w4[1] + w4[2] + w4[3]), EPS);
    li[t] = v / nrm;
    __syncthreads();

    int c = t & 63, ph = t >> 6;
    float a = 0.0f;
#pragma unroll 8
    for (int k = ph * 64; k < ph * 64 + 64; k++) a += li[k] * W2[k * NCLS + c];
    pacc[t] = a;
    __syncthreads();

    float acc = pacc[c] + pacc[64 + c] + b2[c];

    float m = acc;
#pragma unroll
    for (int o = 16; o; o >>= 1) m = fmaxf(m, __shfl_xor_sync(0xffffffffu, m, o));
    if (lane == 0) sm[wid] = m;
    __syncthreads();
    m = fmaxf(sm[0], sm[1]);
    __syncthreads();
    float sh = acc - m;
    float e = expf(sh);
    float ss = e;
#pragma unroll
    for (int o = 16; o; o >>= 1) ss += __shfl_xor_sync(0xffffffffu, ss, o);
    if (lane == 0) sm[wid] = ss;
    __syncthreads();
    ss = sm[0] + sm[1];
    if (t < 64) out[(size_t)row * NCLS + c] = sh - logf(ss);
}

// ---------------- launch: 2-stream fork/join, 9 graph ops (was 12) ------------
extern "C" void kernel_launch(void* const* d_in, const int* in_sizes, int n_in,
                              void* d_out, int out_size) {
    const float* x      = (const float*)d_in[0];
    const float* adj    = (const float*)d_in[1];
    const float* y_lab  = (const float*)d_in[2];
    const int*   idx_tr = (const int*)  d_in[3];
    const float* W0     = (const float*)d_in[4];
    const float* b0     = (const float*)d_in[5];
    const float* W1     = (const float*)d_in[6];
    const float* b1     = (const float*)d_in[7];
    const float* W2     = (const float*)d_in[8];
    const float* b2     = (const float*)d_in[9];
    float* out = (float*)d_out;

    static cudaStream_t s2 = nullptr;
    static cudaEvent_t evFork = nullptr, evExt = nullptr;
    if (s2 == nullptr) {
        cudaStreamCreateWithFlags(&s2, cudaStreamNonBlocking);
        cudaEventCreateWithFlags(&evFork, cudaEventDisableTiming);
        cudaEventCreateWithFlags(&evExt,  cudaEventDisableTiming);
    }

    cudaEventRecord(evFork, 0);
    cudaStreamWaitEvent(s2, evFork, 0);

    extract_adj_kernel<<<1000, 256, 0, s2>>>(adj);
    cudaEventRecord(evExt, s2);

    gemm1_tc<<<NN / 64, 128>>>(x, W0, b0);                       // stream 0
    pseudo_fused<<<NN / 4, dim3(64, 4)>>>(W1, b1, y_lab, idx_tr,
                                          out + (size_t)NN * NCLS);
    cudaStreamWaitEvent(0, evExt, 0);
    ew_prop0<<<NN, 128>>>();
    prop1_final<<<NN, 128>>>(W2, b2, out);
}

// round 13
// speedup vs baseline: 1.0128x; 1.0068x over previous
#include <cuda_runtime.h>
#include <cuda_bf16.h>
#include <math.h>

// Problem constants
#define NN      8000
#define NFEAT   512
#define NHID    128
#define NCLS    64
#define CAP     96
#define EPS     1e-12f
#define NTRAIN  500
#define RPB     4         // rows per block in prop1_final

#define AST 20            // As smem stride (16 + 4 pad)
#define BST 136           // Bs smem stride (128 + 8 pad)

// ---------------- scratch (device globals; no allocation allowed) ------------
__device__ float g_h     [NN * NHID];
__device__ float g_li0   [NN * NHID];
__device__ float g_yhat  [NN * NCLS];
__device__ int   g_cols  [NN * CAP];
__device__ float g_w     [NN * CAP];
__device__ int   g_deg   [NN];

// ---------------- helpers ----------------------------------------------------
__device__ __forceinline__ unsigned f2tf(float f) {
    unsigned u;
    asm("cvt.rna.tf32.f32 %0, %1;" : "=r"(u) : "f"(f));
    return u;
}

#define MMA_TF32(cc, a, b0_, b1_)                                              \
    asm volatile(                                                              \
        "mma.sync.aligned.m16n8k8.row.col.f32.tf32.tf32.f32 "                  \
        "{%0,%1,%2,%3}, {%4,%5,%6,%7}, {%8,%9}, {%0,%1,%2,%3};"                \
        : "+f"(cc[0]), "+f"(cc[1]), "+f"(cc[2]), "+f"(cc[3])                   \
        : "r"(a[0]), "r"(a[1]), "r"(a[2]), "r"(a[3]), "r"(b0_), "r"(b1_))

// =============================================================================
// KERNEL 1: GEMM1 (tensor tf32-split): h = relu(x @ W0 + b0)   [champion verbatim]
// =============================================================================
__global__ __launch_bounds__(128) void gemm1_tc(const float* __restrict__ x,
                                                const float* __restrict__ W0,
                                                const float* __restrict__ b0) {
    __shared__ unsigned Ah[64 * AST], Al[64 * AST];
    __shared__ unsigned Bh[16 * BST], Bl[16 * BST];

    const int tid  = threadIdx.x;
    const int warp = tid >> 5;
    const int lane = tid & 31;
    const int m0   = blockIdx.x * 64;
    const int wm   = (warp & 1) * 32;
    const int wn   = (warp >> 1) * 64;

    float c[2][8][4];
#pragma unroll
    for (int mt = 0; mt < 2; mt++)
#pragma unroll
        for (int nt = 0; nt < 8; nt++)
#pragma unroll
            for (int r = 0; r < 4; r++) c[mt][nt][r] = 0.0f;

    const int ra = tid >> 1, ca = (tid & 1) * 8;
    const int rb = tid >> 3, cb = (tid & 7) * 16;
    float4 xa[2], wb[4];

    {
        const float* xp = x + (size_t)(m0 + ra) * NFEAT + ca;
        xa[0] = *(const float4*)(xp);
        xa[1] = *(const float4*)(xp + 4);
        const float* wp = W0 + (size_t)rb * NHID + cb;
#pragma unroll
        for (int i = 0; i < 4; i++) wb[i] = *(const float4*)(wp + i * 4);
    }

    for (int it = 0; it < 32; it++) {
        {
            const float* av = (const float*)xa;
#pragma unroll
            for (int j = 0; j < 8; j++) {
                float v  = av[j];
                unsigned hb = f2tf(v);
                Ah[ra * AST + ca + j] = hb;
                Al[ra * AST + ca + j] = f2tf(v - __uint_as_float(hb));
            }
            const float* bv = (const float*)wb;
#pragma unroll
            for (int j = 0; j < 16; j++) {
                float v  = bv[j];
                unsigned hb = f2tf(v);
                Bh[rb * BST + cb + j] = hb;
                Bl[rb * BST + cb + j] = f2tf(v - __uint_as_float(hb));
            }
        }
        __syncthreads();

        if (it < 31) {
            int k0 = (it + 1) * 16;
            const float* xp = x + (size_t)(m0 + ra) * NFEAT + k0 + ca;
            xa[0] = *(const float4*)(xp);
            xa[1] = *(const float4*)(xp + 4);
            const float* wp = W0 + (size_t)(k0 + rb) * NHID + cb;
#pragma unroll
            for (int i = 0; i < 4; i++) wb[i] = *(const float4*)(wp + i * 4);
        }

#pragma unroll
        for (int ks = 0; ks < 16; ks += 8) {
            unsigned ah[2][4], al[2][4];
            const int arow = wm + (lane >> 2);
            const int ac   = ks + (lane & 3);
#pragma unroll
            for (int mt = 0; mt < 2; mt++) {
                int r = arow + mt * 16;
                ah[mt][0] = Ah[r * AST + ac];
                ah[mt][1] = Ah[(r + 8) * AST + ac];
                ah[mt][2] = Ah[r * AST + ac + 4];
                ah[mt][3] = Ah[(r + 8) * AST + ac + 4];
                al[mt][0] = Al[r * AST + ac];
                al[mt][1] = Al[(r + 8) * AST + ac];
                al[mt][2] = Al[r * AST + ac + 4];
                al[mt][3] = Al[(r + 8) * AST + ac + 4];
            }
#pragma unroll
            for (int nt = 0; nt < 8; nt++) {
                const int bn = wn + nt * 8 + (lane >> 2);
                const int bk = ks + (lane & 3);
                unsigned bh0 = Bh[bk * BST + bn];
                unsigned bh1 = Bh[(bk + 4) * BST + bn];
                unsigned bl0 = Bl[bk * BST + bn];
                unsigned bl1 = Bl[(bk + 4) * BST + bn];
#pragma unroll
                for (int mt = 0; mt < 2; mt++) {
                    MMA_TF32(c[mt][nt], ah[mt], bh0, bh1);
                    MMA_TF32(c[mt][nt], ah[mt], bl0, bl1);
                    MMA_TF32(c[mt][nt], al[mt], bh0, bh1);
                }
            }
        }
        __syncthreads();
    }

#pragma unroll
    for (int nt = 0; nt < 8; nt++) {
        int col = wn + nt * 8 + 2 * (lane & 3);
        float bias0 = b0[col], bias1 = b0[col + 1];
#pragma unroll
        for (int mt = 0; mt < 2; mt++) {
            int r = m0 + wm + mt * 16 + (lane >> 2);
            g_h[(size_t)r * NHID + col]           = fmaxf(c[mt][nt][0] + bias0, 0.0f);
            g_h[(size_t)r * NHID + col + 1]       = fmaxf(c[mt][nt][1] + bias1, 0.0f);
            g_h[(size_t)(r + 8) * NHID + col]     = fmaxf(c[mt][nt][2] + bias0, 0.0f);
            g_h[(size_t)(r + 8) * NHID + col + 1] = fmaxf(c[mt][nt][3] + bias1, 0.0f);
        }
    }
}

// =============================================================================
// KERNEL 2: adjacency extraction (1 warp/row)   [champion verbatim]
// =============================================================================
__global__ __launch_bounds__(256) void extract_adj_kernel(const float* __restrict__ adj) {
    int row_id = blockIdx.x * 8 + (threadIdx.x >> 5);
    int lane = threadIdx.x & 31;
    const float* row = adj + (size_t)row_id * NN;
    int base = 0;
    for (int c0 = 0; c0 < 7936; c0 += 128) {
        float4 v = *(const float4*)(row + c0 + lane * 4);
        unsigned m4 = (v.x != 0.0f) | ((v.y != 0.0f) << 1) |
                      ((v.z != 0.0f) << 2) | ((v.w != 0.0f) << 3);
        unsigned act = __ballot_sync(0xffffffffu, m4 != 0);
        if (act == 0) continue;
        int nz = __popc(m4);
        while (act) {
            int l   = __ffs(act) - 1;
            int c_l = __shfl_sync(0xffffffffu, nz, l);
            if (lane == l) {
                int p = base;
                int col = c0 + lane * 4;
                if (m4 & 1) { if (p < CAP) g_cols[row_id * CAP + p] = col;     p++; }
                if (m4 & 2) { if (p < CAP) g_cols[row_id * CAP + p] = col + 1; p++; }
                if (m4 & 4) { if (p < CAP) g_cols[row_id * CAP + p] = col + 2; p++; }
                if (m4 & 8) { if (p < CAP) g_cols[row_id * CAP + p] = col + 3; }
            }
            base += c_l;
            act &= act - 1;
        }
    }
    {
        float2 v = *(const float2*)(row + 7936 + lane * 2);
        unsigned m2 = (v.x != 0.0f) | ((v.y != 0.0f) << 1);
        unsigned act = __ballot_sync(0xffffffffu, m2 != 0);
        int nz = __popc(m2);
        while (act) {
            int l   = __ffs(act) - 1;
            int c_l = __shfl_sync(0xffffffffu, nz, l);
            if (lane == l) {
                int p = base;
                int col = 7936 + lane * 2;
                if (m2 & 1) { if (p < CAP) g_cols[row_id * CAP + p] = col;     p++; }
                if (m2 & 2) { if (p < CAP) g_cols[row_id * CAP + p] = col + 1; }
            }
            base += c_l;
            act &= act - 1;
        }
    }
    if (lane == 0) g_deg[row_id] = base < CAP ? base : CAP;
}

// =============================================================================
// KERNEL 3: Pseudo fused (in-kernel cnt)   [R12 verbatim]
// =============================================================================
__global__ void pseudo_fused(const float* __restrict__ W1,
                             const float* __restrict__ b1,
                             const float* __restrict__ y_label,
                             const int*   __restrict__ idx_tr,
                             float* __restrict__ out_pseudo) {
    int ry = threadIdx.y, c = threadIdx.x;
    int row = blockIdx.x * 4 + ry;
    int tid = ry * 64 + c;
    __shared__ float hr[4][128];
    __shared__ int   idxs[NTRAIN];
    __shared__ float sm[4][2];
    __shared__ int   scnt[4][2];

    hr[ry][c]      = g_h[(size_t)row * NHID + c];
    hr[ry][c + 64] = g_h[(size_t)row * NHID + c + 64];
    for (int i = tid; i < NTRAIN; i += 256) idxs[i] = idx_tr[i];
    __syncthreads();

    float acc = b1[c];
#pragma unroll 8
    for (int k = 0; k < NHID; k++) acc += hr[ry][k] * W1[k * NCLS + c];

    int wu = c >> 5, lane = c & 31;
    int cnt = 0;
    for (int i = c; i < NTRAIN; i += 64) cnt += (idxs[i] == row);
#pragma unroll
    for (int o = 16; o; o >>= 1) cnt += __shfl_xor_sync(0xffffffffu, cnt, o);
    if (lane == 0) scnt[ry][wu] = cnt;
    __syncthreads();
    cnt = scnt[ry][0] + scnt[ry][1];
    if (cnt) acc += 0.1f * (float)cnt * y_label[(size_t)row * NCLS + c];

    out_pseudo[(size_t)row * NCLS + c] = acc;

    float m = acc;
#pragma unroll
    for (int o = 16; o; o >>= 1) m = fmaxf(m, __shfl_xor_sync(0xffffffffu, m, o));
    if (lane == 0) sm[ry][wu] = m;
    __syncthreads();
    m = fmaxf(sm[ry][0], sm[ry][1]);
    __syncthreads();
    float e = expf(acc - m);
    float s = e;
#pragma unroll
    for (int o = 16; o; o >>= 1) s += __shfl_xor_sync(0xffffffffu, s, o);
    if (lane == 0) sm[ry][wu] = s;
    __syncthreads();
    s = sm[ry][0] + sm[ry][1];
    g_yhat[(size_t)row * NCLS + c] = e / s;
}

// =============================================================================
// KERNEL 4: edge weights + propagation layer 0   [champion verbatim]
// =============================================================================
__global__ __launch_bounds__(128) void ew_prop0() {
    int row = blockIdx.x;
    __shared__ float yi[NCLS];
    __shared__ int   cs[CAP];
    __shared__ float ws[CAP];
    __shared__ float w4[4];
    __shared__ float ssum;
    int t = threadIdx.x;
    int wid = t >> 5, lane = t & 31;
    int deg = g_deg[row];
    if (t < NCLS) yi[t] = g_yhat[(size_t)row * NCLS + t];
    if (t < deg)  cs[t] = g_cols[row * CAP + t];
    __syncthreads();

    for (int n = wid; n < deg; n += 4) {
        const float* yj = g_yhat + (size_t)cs[n] * NCLS;
        float p = yi[lane] * yj[lane] + yi[lane + 32] * yj[lane + 32];
#pragma unroll
        for (int o = 16; o; o >>= 1) p += __shfl_down_sync(0xffffffffu, p, o);
        if (lane == 0) ws[n] = p;
    }
    __syncthreads();
    if (t == 0) {
        float s = 0.0f;
        for (int n = 0; n < deg; n++) s += ws[n];
        ssum = fmaxf(s, EPS);
    }
    __syncthreads();
    if (t < deg) {
        float wn = ws[t] / ssum;
        ws[t] = wn;
        g_w[row * CAP + t] = wn;
    }
    __syncthreads();

    float s = 0.0f;
    int n = 0;
    for (; n + 4 <= deg; n += 4) {
        float a0 = g_h[(size_t)cs[n]     * NHID + t];
        float a1 = g_h[(size_t)cs[n + 1] * NHID + t];
        float a2 = g_h[(size_t)cs[n + 2] * NHID + t];
        float a3 = g_h[(size_t)cs[n + 3] * NHID + t];
        s += ws[n] * a0 + ws[n + 1] * a1 + ws[n + 2] * a2 + ws[n + 3] * a3;
    }
    for (; n < deg; n++) s += ws[n] * g_h[(size_t)cs[n] * NHID + t];

    float v = 0.9f * s + 0.1f * g_h[(size_t)row * NHID + t];

    float q = v * v;
#pragma unroll
    for (int o = 16; o; o >>= 1) q += __shfl_xor_sync(0xffffffffu, q, o);
    if (lane == 0) w4[wid] = q;
    __syncthreads();
    float nrm = fmaxf(sqrtf(w4[0] + w4[1] + w4[2] + w4[3]), EPS);
    g_li0[(size_t)row * NHID + t] = v / nrm;
}

// =============================================================================
// KERNEL 5: propagation layer 1 + log_softmax(li1 @ W2 + b2)
// [ONLY rewrite this round: 4 rows/block — W2 L2 traffic /4, W2 register reuse]
// =============================================================================
__global__ __launch_bounds__(128) void prop1_final(const float* __restrict__ W2,
                                                   const float* __restrict__ b2,
                                                   float* __restrict__ out) {
    int row0 = blockIdx.x * RPB;
    __shared__ int   cs  [RPB][CAP];
    __shared__ float ws  [RPB][CAP];
    __shared__ float li  [RPB][NHID];
    __shared__ float pacc[RPB][NHID];
    __shared__ float w4  [RPB][4];
    __shared__ float smx [RPB][2];
    int t = threadIdx.x;
    int wid = t >> 5, lane = t & 31;

    int degs[RPB];
#pragma unroll
    for (int r = 0; r < RPB; r++) {
        degs[r] = g_deg[row0 + r];
        if (t < degs[r]) {
            cs[r][t] = g_cols[(row0 + r) * CAP + t];
            ws[r][t] = g_w  [(row0 + r) * CAP + t];
        }
    }
    __syncthreads();

    // SpMM + residual + L2 norm, 4 independent rows per thread (MLP ~16)
    float v[RPB];
#pragma unroll
    for (int r = 0; r < RPB; r++) {
        int deg = degs[r];
        float s = 0.0f;
        int n = 0;
        for (; n + 4 <= deg; n += 4) {
            float a0 = g_li0[(size_t)cs[r][n]     * NHID + t];
            float a1 = g_li0[(size_t)cs[r][n + 1] * NHID + t];
            float a2 = g_li0[(size_t)cs[r][n + 2] * NHID + t];
            float a3 = g_li0[(size_t)cs[r][n + 3] * NHID + t];
            s += ws[r][n] * a0 + ws[r][n + 1] * a1 + ws[r][n + 2] * a2 + ws[r][n + 3] * a3;
        }
        for (; n < deg; n++) s += ws[r][n] * g_li0[(size_t)cs[r][n] * NHID + t];
        v[r] = 0.9f * s + 0.1f * g_h[(size_t)(row0 + r) * NHID + t];
        float q = v[r] * v[r];
#pragma unroll
        for (int o = 16; o; o >>= 1) q += __shfl_xor_sync(0xffffffffu, q, o);
        if (lane == 0) w4[r][wid] = q;
    }
    __syncthreads();
#pragma unroll
    for (int r = 0; r < RPB; r++) {
        float nrm = fmaxf(sqrtf(w4[r][0] + w4[r][1] + w4[r][2] + w4[r][3]), EPS);
        li[r][t] = v[r] / nrm;
    }
    __syncthreads();

    // split-K GEMV for 4 rows: each W2 load feeds 4 accumulators
    int c = t & 63, ph = t >> 6;
    float acc[RPB] = {0.f, 0.f, 0.f, 0.f};
#pragma unroll 8
    for (int k = ph * 64; k < ph * 64 + 64; k++) {
        float w = W2[k * NCLS + c];
#pragma unroll
        for (int r = 0; r < RPB; r++) acc[r] += li[r][k] * w;
    }
#pragma unroll
    for (int r = 0; r < RPB; r++) pacc[r][t] = acc[r];
    __syncthreads();

    // log_softmax: pass p handles rows {0,1} then {2,3};
    // thread group rr = t>>6 (64 threads = warps {2rr, 2rr+1}) owns row rr+2p
    float bias = b2[c];
#pragma unroll
    for (int p = 0; p < 2; p++) {
        int R = (t >> 6) + 2 * p;
        float accv = pacc[R][c] + pacc[R][64 + c] + bias;
        float m = accv;
#pragma unroll
        for (int o = 16; o; o >>= 1) m = fmaxf(m, __shfl_xor_sync(0xffffffffu, m, o));
        if (lane == 0) smx[R][wid & 1] = m;
        __syncthreads();
        m = fmaxf(smx[R][0], smx[R][1]);
        __syncthreads();
        float sh = accv - m;
        float e = expf(sh);
        float ss = e;
#pragma unroll
        for (int o = 16; o; o >>= 1) ss += __shfl_xor_sync(0xffffffffu, ss, o);
        if (lane == 0) smx[R][wid & 1] = ss;
        __syncthreads();
        ss = smx[R][0] + smx[R][1];
        out[(size_t)(row0 + R) * NCLS + c] = sh - logf(ss);
        __syncthreads();
    }
}

// ---------------- launch: 2-stream fork/join --------------------------------
extern "C" void kernel_launch(void* const* d_in, const int* in_sizes, int n_in,
                              void* d_out, int out_size) {
    const float* x      = (const float*)d_in[0];
    const float* adj    = (const float*)d_in[1];
    const float* y_lab  = (const float*)d_in[2];
    const int*   idx_tr = (const int*)  d_in[3];
    const float* W0     = (const float*)d_in[4];
    const float* b0     = (const float*)d_in[5];
    const float* W1     = (const float*)d_in[6];
    const float* b1     = (const float*)d_in[7];
    const float* W2     = (const float*)d_in[8];
    const float* b2     = (const float*)d_in[9];
    float* out = (float*)d_out;

    static cudaStream_t s2 = nullptr;
    static cudaEvent_t evFork = nullptr, evExt = nullptr;
    if (s2 == nullptr) {
        cudaStreamCreateWithFlags(&s2, cudaStreamNonBlocking);
        cudaEventCreateWithFlags(&evFork, cudaEventDisableTiming);
        cudaEventCreateWithFlags(&evExt,  cudaEventDisableTiming);
    }

    cudaEventRecord(evFork, 0);
    cudaStreamWaitEvent(s2, evFork, 0);

    extract_adj_kernel<<<1000, 256, 0, s2>>>(adj);
    cudaEventRecord(evExt, s2);

    gemm1_tc<<<NN / 64, 128>>>(x, W0, b0);                       // stream 0
    pseudo_fused<<<NN / 4, dim3(64, 4)>>>(W1, b1, y_lab, idx_tr,
                                          out + (size_t)NN * NCLS);
    cudaStreamWaitEvent(0, evExt, 0);
    ew_prop0<<<NN, 128>>>();
    prop1_final<<<NN / RPB, 128>>>(W2, b2, out);
}

// round 14
// speedup vs baseline: 1.0222x; 1.0092x over previous
#include <cuda_runtime.h>
#include <cuda_bf16.h>
#include <math.h>

// Problem constants
#define NN      8000
#define NFEAT   512
#define NHID    128
#define NCLS    64
#define CAP     96
#define EPS     1e-12f
#define NTRAIN  500
#define RPB     4         // rows per block in prop kernels

#define AST 20            // As smem stride (16 + 4 pad)
#define BST 136           // Bs smem stride (128 + 8 pad)

// ---------------- scratch (device globals; no allocation allowed) ------------
__device__ float g_h     [NN * NHID];
__device__ float g_li0   [NN * NHID];
__device__ float g_yhat  [NN * NCLS];
__device__ int   g_cols  [NN * CAP];
__device__ float g_w     [NN * CAP];
__device__ int   g_deg   [NN];

// ---------------- helpers ----------------------------------------------------
__device__ __forceinline__ unsigned f2tf(float f) {
    unsigned u;
    asm("cvt.rna.tf32.f32 %0, %1;" : "=r"(u) : "f"(f));
    return u;
}

#define MMA_TF32(cc, a, b0_, b1_)                                              \
    asm volatile(                                                              \
        "mma.sync.aligned.m16n8k8.row.col.f32.tf32.tf32.f32 "                  \
        "{%0,%1,%2,%3}, {%4,%5,%6,%7}, {%8,%9}, {%0,%1,%2,%3};"                \
        : "+f"(cc[0]), "+f"(cc[1]), "+f"(cc[2]), "+f"(cc[3])                   \
        : "r"(a[0]), "r"(a[1]), "r"(a[2]), "r"(a[3]), "r"(b0_), "r"(b1_))

// =============================================================================
// KERNEL 1: GEMM1 (tensor tf32-split): h = relu(x @ W0 + b0)   [champion verbatim]
// =============================================================================
__global__ __launch_bounds__(128) void gemm1_tc(const float* __restrict__ x,
                                                const float* __restrict__ W0,
                                                const float* __restrict__ b0) {
    __shared__ unsigned Ah[64 * AST], Al[64 * AST];
    __shared__ unsigned Bh[16 * BST], Bl[16 * BST];

    const int tid  = threadIdx.x;
    const int warp = tid >> 5;
    const int lane = tid & 31;
    const int m0   = blockIdx.x * 64;
    const int wm   = (warp & 1) * 32;
    const int wn   = (warp >> 1) * 64;

    float c[2][8][4];
#pragma unroll
    for (int mt = 0; mt < 2; mt++)
#pragma unroll
        for (int nt = 0; nt < 8; nt++)
#pragma unroll
            for (int r = 0; r < 4; r++) c[mt][nt][r] = 0.0f;

    const int ra = tid >> 1, ca = (tid & 1) * 8;
    const int rb = tid >> 3, cb = (tid & 7) * 16;
    float4 xa[2], wb[4];

    {
        const float* xp = x + (size_t)(m0 + ra) * NFEAT + ca;
        xa[0] = *(const float4*)(xp);
        xa[1] = *(const float4*)(xp + 4);
        const float* wp = W0 + (size_t)rb * NHID + cb;
#pragma unroll
        for (int i = 0; i < 4; i++) wb[i] = *(const float4*)(wp + i * 4);
    }

    for (int it = 0; it < 32; it++) {
        {
            const float* av = (const float*)xa;
#pragma unroll
            for (int j = 0; j < 8; j++) {
                float v  = av[j];
                unsigned hb = f2tf(v);
                Ah[ra * AST + ca + j] = hb;
                Al[ra * AST + ca + j] = f2tf(v - __uint_as_float(hb));
            }
            const float* bv = (const float*)wb;
#pragma unroll
            for (int j = 0; j < 16; j++) {
                float v  = bv[j];
                unsigned hb = f2tf(v);
                Bh[rb * BST + cb + j] = hb;
                Bl[rb * BST + cb + j] = f2tf(v - __uint_as_float(hb));
            }
        }
        __syncthreads();

        if (it < 31) {
            int k0 = (it + 1) * 16;
            const float* xp = x + (size_t)(m0 + ra) * NFEAT + k0 + ca;
            xa[0] = *(const float4*)(xp);
            xa[1] = *(const float4*)(xp + 4);
            const float* wp = W0 + (size_t)(k0 + rb) * NHID + cb;
#pragma unroll
            for (int i = 0; i < 4; i++) wb[i] = *(const float4*)(wp + i * 4);
        }

#pragma unroll
        for (int ks = 0; ks < 16; ks += 8) {
            unsigned ah[2][4], al[2][4];
            const int arow = wm + (lane >> 2);
            const int ac   = ks + (lane & 3);
#pragma unroll
            for (int mt = 0; mt < 2; mt++) {
                int r = arow + mt * 16;
                ah[mt][0] = Ah[r * AST + ac];
                ah[mt][1] = Ah[(r + 8) * AST + ac];
                ah[mt][2] = Ah[r * AST + ac + 4];
                ah[mt][3] = Ah[(r + 8) * AST + ac + 4];
                al[mt][0] = Al[r * AST + ac];
                al[mt][1] = Al[(r + 8) * AST + ac];
                al[mt][2] = Al[r * AST + ac + 4];
                al[mt][3] = Al[(r + 8) * AST + ac + 4];
            }
#pragma unroll
            for (int nt = 0; nt < 8; nt++) {
                const int bn = wn + nt * 8 + (lane >> 2);
                const int bk = ks + (lane & 3);
                unsigned bh0 = Bh[bk * BST + bn];
                unsigned bh1 = Bh[(bk + 4) * BST + bn];
                unsigned bl0 = Bl[bk * BST + bn];
                unsigned bl1 = Bl[(bk + 4) * BST + bn];
#pragma unroll
                for (int mt = 0; mt < 2; mt++) {
                    MMA_TF32(c[mt][nt], ah[mt], bh0, bh1);
                    MMA_TF32(c[mt][nt], ah[mt], bl0, bl1);
                    MMA_TF32(c[mt][nt], al[mt], bh0, bh1);
                }
            }
        }
        __syncthreads();
    }

#pragma unroll
    for (int nt = 0; nt < 8; nt++) {
        int col = wn + nt * 8 + 2 * (lane & 3);
        float bias0 = b0[col], bias1 = b0[col + 1];
#pragma unroll
        for (int mt = 0; mt < 2; mt++) {
            int r = m0 + wm + mt * 16 + (lane >> 2);
            g_h[(size_t)r * NHID + col]           = fmaxf(c[mt][nt][0] + bias0, 0.0f);
            g_h[(size_t)r * NHID + col + 1]       = fmaxf(c[mt][nt][1] + bias1, 0.0f);
            g_h[(size_t)(r + 8) * NHID + col]     = fmaxf(c[mt][nt][2] + bias0, 0.0f);
            g_h[(size_t)(r + 8) * NHID + col + 1] = fmaxf(c[mt][nt][3] + bias1, 0.0f);
        }
    }
}

// =============================================================================
// KERNEL 2: adjacency extraction (1 warp/row)   [champion verbatim]
// =============================================================================
__global__ __launch_bounds__(256) void extract_adj_kernel(const float* __restrict__ adj) {
    int row_id = blockIdx.x * 8 + (threadIdx.x >> 5);
    int lane = threadIdx.x & 31;
    const float* row = adj + (size_t)row_id * NN;
    int base = 0;
    for (int c0 = 0; c0 < 7936; c0 += 128) {
        float4 v = *(const float4*)(row + c0 + lane * 4);
        unsigned m4 = (v.x != 0.0f) | ((v.y != 0.0f) << 1) |
                      ((v.z != 0.0f) << 2) | ((v.w != 0.0f) << 3);
        unsigned act = __ballot_sync(0xffffffffu, m4 != 0);
        if (act == 0) continue;
        int nz = __popc(m4);
        while (act) {
            int l   = __ffs(act) - 1;
            int c_l = __shfl_sync(0xffffffffu, nz, l);
            if (lane == l) {
                int p = base;
                int col = c0 + lane * 4;
                if (m4 & 1) { if (p < CAP) g_cols[row_id * CAP + p] = col;     p++; }
                if (m4 & 2) { if (p < CAP) g_cols[row_id * CAP + p] = col + 1; p++; }
                if (m4 & 4) { if (p < CAP) g_cols[row_id * CAP + p] = col + 2; p++; }
                if (m4 & 8) { if (p < CAP) g_cols[row_id * CAP + p] = col + 3; }
            }
            base += c_l;
            act &= act - 1;
        }
    }
    {
        float2 v = *(const float2*)(row + 7936 + lane * 2);
        unsigned m2 = (v.x != 0.0f) | ((v.y != 0.0f) << 1);
        unsigned act = __ballot_sync(0xffffffffu, m2 != 0);
        int nz = __popc(m2);
        while (act) {
            int l   = __ffs(act) - 1;
            int c_l = __shfl_sync(0xffffffffu, nz, l);
            if (lane == l) {
                int p = base;
                int col = 7936 + lane * 2;
                if (m2 & 1) { if (p < CAP) g_cols[row_id * CAP + p] = col;     p++; }
                if (m2 & 2) { if (p < CAP) g_cols[row_id * CAP + p] = col + 1; }
            }
            base += c_l;
            act &= act - 1;
        }
    }
    if (lane == 0) g_deg[row_id] = base < CAP ? base : CAP;
}

// =============================================================================
// KERNEL 3: Pseudo fused (in-kernel cnt)   [R12 verbatim]
// =============================================================================
__global__ void pseudo_fused(const float* __restrict__ W1,
                             const float* __restrict__ b1,
                             const float* __restrict__ y_label,
                             const int*   __restrict__ idx_tr,
                             float* __restrict__ out_pseudo) {
    int ry = threadIdx.y, c = threadIdx.x;
    int row = blockIdx.x * 4 + ry;
    int tid = ry * 64 + c;
    __shared__ float hr[4][128];
    __shared__ int   idxs[NTRAIN];
    __shared__ float sm[4][2];
    __shared__ int   scnt[4][2];

    hr[ry][c]      = g_h[(size_t)row * NHID + c];
    hr[ry][c + 64] = g_h[(size_t)row * NHID + c + 64];
    for (int i = tid; i < NTRAIN; i += 256) idxs[i] = idx_tr[i];
    __syncthreads();

    float acc = b1[c];
#pragma unroll 8
    for (int k = 0; k < NHID; k++) acc += hr[ry][k] * W1[k * NCLS + c];

    int wu = c >> 5, lane = c & 31;
    int cnt = 0;
    for (int i = c; i < NTRAIN; i += 64) cnt += (idxs[i] == row);
#pragma unroll
    for (int o = 16; o; o >>= 1) cnt += __shfl_xor_sync(0xffffffffu, cnt, o);
    if (lane == 0) scnt[ry][wu] = cnt;
    __syncthreads();
    cnt = scnt[ry][0] + scnt[ry][1];
    if (cnt) acc += 0.1f * (float)cnt * y_label[(size_t)row * NCLS + c];

    out_pseudo[(size_t)row * NCLS + c] = acc;

    float m = acc;
#pragma unroll
    for (int o = 16; o; o >>= 1) m = fmaxf(m, __shfl_xor_sync(0xffffffffu, m, o));
    if (lane == 0) sm[ry][wu] = m;
    __syncthreads();
    m = fmaxf(sm[ry][0], sm[ry][1]);
    __syncthreads();
    float e = expf(acc - m);
    float s = e;
#pragma unroll
    for (int o = 16; o; o >>= 1) s += __shfl_xor_sync(0xffffffffu, s, o);
    if (lane == 0) sm[ry][wu] = s;
    __syncthreads();
    s = sm[ry][0] + sm[ry][1];
    g_yhat[(size_t)row * NCLS + c] = e / s;
}

// =============================================================================
// KERNEL 4: edge weights + propagation layer 0
// [ONLY rewrite this round: 4 rows/block, warp-per-row edge weights (warp-local
//  normalize, no block syncs in weight phase), 4-row interleaved SpMM]
// =============================================================================
__global__ __launch_bounds__(128) void ew_prop0() {
    int row0 = blockIdx.x * RPB;
    __shared__ float yi[RPB][NCLS];
    __shared__ int   cs[RPB][CAP];
    __shared__ float ws[RPB][CAP];
    __shared__ float w4[RPB][4];
    int t = threadIdx.x;
    int wid = t >> 5, lane = t & 31;

    int degs[RPB];
#pragma unroll
    for (int r = 0; r < RPB; r++) {
        degs[r] = g_deg[row0 + r];
        if (t < degs[r]) cs[r][t] = g_cols[(row0 + r) * CAP + t];
    }
    // yi: 4 rows x 64 cols = 256 floats, 128 threads -> 2 loads each
    yi[t >> 6][t & 63]       = g_yhat[(size_t)(row0 + (t >> 6)) * NCLS + (t & 63)];
    yi[2 + (t >> 6)][t & 63] = g_yhat[(size_t)(row0 + 2 + (t >> 6)) * NCLS + (t & 63)];
    __syncthreads();

    // edge weights: warp `wid` owns row row0+wid, 2x-unrolled neighbor dots
    {
        int deg = degs[wid];
        float my0 = yi[wid][lane], my1 = yi[wid][lane + 32];
        int n = 0;
        for (; n + 2 <= deg; n += 2) {
            const float* yj0 = g_yhat + (size_t)cs[wid][n]     * NCLS;
            const float* yj1 = g_yhat + (size_t)cs[wid][n + 1] * NCLS;
            float p0 = my0 * yj0[lane] + my1 * yj0[lane + 32];
            float p1 = my0 * yj1[lane] + my1 * yj1[lane + 32];
#pragma unroll
            for (int o = 16; o; o >>= 1) {
                p0 += __shfl_down_sync(0xffffffffu, p0, o);
                p1 += __shfl_down_sync(0xffffffffu, p1, o);
            }
            if (lane == 0) { ws[wid][n] = p0; ws[wid][n + 1] = p1; }
        }
        for (; n < deg; n++) {
            const float* yj = g_yhat + (size_t)cs[wid][n] * NCLS;
            float p = my0 * yj[lane] + my1 * yj[lane + 32];
#pragma unroll
            for (int o = 16; o; o >>= 1) p += __shfl_down_sync(0xffffffffu, p, o);
            if (lane == 0) ws[wid][n] = p;
        }
        __syncwarp();
        // warp-local sum + normalize (serial-sum order preserved per original
        // would differ; use lane-strided sum — all-nonneg, rel_err budget huge)
        float s = (lane < deg ? ws[wid][lane] : 0.0f)
                + (lane + 32 < deg ? ws[wid][lane + 32] : 0.0f)
                + (lane + 64 < deg ? ws[wid][lane + 64] : 0.0f);
#pragma unroll
        for (int o = 16; o; o >>= 1) s += __shfl_xor_sync(0xffffffffu, s, o);
        float ssum = fmaxf(s, EPS);
        for (int i = lane; i < deg; i += 32) {
            float wn = ws[wid][i] / ssum;
            ws[wid][i] = wn;
            g_w[(row0 + wid) * CAP + i] = wn;
        }
    }
    __syncthreads();

    // SpMM + residual + L2 norm, 4 independent rows per thread (high MLP)
    float v[RPB];
#pragma unroll
    for (int r = 0; r < RPB; r++) {
        int deg = degs[r];
        float s = 0.0f;
        int n = 0;
        for (; n + 4 <= deg; n += 4) {
            float a0 = g_h[(size_t)cs[r][n]     * NHID + t];
            float a1 = g_h[(size_t)cs[r][n + 1] * NHID + t];
            float a2 = g_h[(size_t)cs[r][n + 2] * NHID + t];
            float a3 = g_h[(size_t)cs[r][n + 3] * NHID + t];
            s += ws[r][n] * a0 + ws[r][n + 1] * a1 + ws[r][n + 2] * a2 + ws[r][n + 3] * a3;
        }
        for (; n < deg; n++) s += ws[r][n] * g_h[(size_t)cs[r][n] * NHID + t];
        v[r] = 0.9f * s + 0.1f * g_h[(size_t)(row0 + r) * NHID + t];
        float q = v[r] * v[r];
#pragma unroll
        for (int o = 16; o; o >>= 1) q += __shfl_xor_sync(0xffffffffu, q, o);
        if (lane == 0) w4[r][wid] = q;
    }
    __syncthreads();
#pragma unroll
    for (int r = 0; r < RPB; r++) {
        float nrm = fmaxf(sqrtf(w4[r][0] + w4[r][1] + w4[r][2] + w4[r][3]), EPS);
        g_li0[(size_t)(row0 + r) * NHID + t] = v[r] / nrm;
    }
}

// =============================================================================
// KERNEL 5: propagation layer 1 + log_softmax (4 rows/block)   [R13 verbatim]
// =============================================================================
__global__ __launch_bounds__(128) void prop1_final(const float* __restrict__ W2,
                                                   const float* __restrict__ b2,
                                                   float* __restrict__ out) {
    int row0 = blockIdx.x * RPB;
    __shared__ int   cs  [RPB][CAP];
    __shared__ float ws  [RPB][CAP];
    __shared__ float li  [RPB][NHID];
    __shared__ float pacc[RPB][NHID];
    __shared__ float w4  [RPB][4];
    __shared__ float smx [RPB][2];
    int t = threadIdx.x;
    int wid = t >> 5, lane = t & 31;

    int degs[RPB];
#pragma unroll
    for (int r = 0; r < RPB; r++) {
        degs[r] = g_deg[row0 + r];
        if (t < degs[r]) {
            cs[r][t] = g_cols[(row0 + r) * CAP + t];
            ws[r][t] = g_w  [(row0 + r) * CAP + t];
        }
    }
    __syncthreads();

    float v[RPB];
#pragma unroll
    for (int r = 0; r < RPB; r++) {
        int deg = degs[r];
        float s = 0.0f;
        int n = 0;
        for (; n + 4 <= deg; n += 4) {
            float a0 = g_li0[(size_t)cs[r][n]     * NHID + t];
            float a1 = g_li0[(size_t)cs[r][n + 1] * NHID + t];
            float a2 = g_li0[(size_t)cs[r][n + 2] * NHID + t];
            float a3 = g_li0[(size_t)cs[r][n + 3] * NHID + t];
            s += ws[r][n] * a0 + ws[r][n + 1] * a1 + ws[r][n + 2] * a2 + ws[r][n + 3] * a3;
        }
        for (; n < deg; n++) s += ws[r][n] * g_li0[(size_t)cs[r][n] * NHID + t];
        v[r] = 0.9f * s + 0.1f * g_h[(size_t)(row0 + r) * NHID + t];
        float q = v[r] * v[r];
#pragma unroll
        for (int o = 16; o; o >>= 1) q += __shfl_xor_sync(0xffffffffu, q, o);
        if (lane == 0) w4[r][wid] = q;
    }
    __syncthreads();
#pragma unroll
    for (int r = 0; r < RPB; r++) {
        float nrm = fmaxf(sqrtf(w4[r][0] + w4[r][1] + w4[r][2] + w4[r][3]), EPS);
        li[r][t] = v[r] / nrm;
    }
    __syncthreads();

    int c = t & 63, ph = t >> 6;
    float acc[RPB] = {0.f, 0.f, 0.f, 0.f};
#pragma unroll 8
    for (int k = ph * 64; k < ph * 64 + 64; k++) {
        float w = W2[k * NCLS + c];
#pragma unroll
        for (int r = 0; r < RPB; r++) acc[r] += li[r][k] * w;
    }
#pragma unroll
    for (int r = 0; r < RPB; r++) pacc[r][t] = acc[r];
    __syncthreads();

    float bias = b2[c];
#pragma unroll
    for (int p = 0; p < 2; p++) {
        int R = (t >> 6) + 2 * p;
        float accv = pacc[R][c] + pacc[R][64 + c] + bias;
        float m = accv;
#pragma unroll
        for (int o = 16; o; o >>= 1) m = fmaxf(m, __shfl_xor_sync(0xffffffffu, m, o));
        if (lane == 0) smx[R][wid & 1] = m;
        __syncthreads();
        m = fmaxf(smx[R][0], smx[R][1]);
        __syncthreads();
        float sh = accv - m;
        float e = expf(sh);
        float ss = e;
#pragma unroll
        for (int o = 16; o; o >>= 1) ss += __shfl_xor_sync(0xffffffffu, ss, o);
        if (lane == 0) smx[R][wid & 1] = ss;
        __syncthreads();
        ss = smx[R][0] + smx[R][1];
        out[(size_t)(row0 + R) * NCLS + c] = sh - logf(ss);
        __syncthreads();
    }
}

// ---------------- launch: 2-stream fork/join --------------------------------
extern "C" void kernel_launch(void* const* d_in, const int* in_sizes, int n_in,
                              void* d_out, int out_size) {
    const float* x      = (const float*)d_in[0];
    const float* adj    = (const float*)d_in[1];
    const float* y_lab  = (const float*)d_in[2];
    const int*   idx_tr = (const int*)  d_in[3];
    const float* W0     = (const float*)d_in[4];
    const float* b0     = (const float*)d_in[5];
    const float* W1     = (const float*)d_in[6];
    const float* b1     = (const float*)d_in[7];
    const float* W2     = (const float*)d_in[8];
    const float* b2     = (const float*)d_in[9];
    float* out = (float*)d_out;

    static cudaStream_t s2 = nullptr;
    static cudaEvent_t evFork = nullptr, evExt = nullptr;
    if (s2 == nullptr) {
        cudaStreamCreateWithFlags(&s2, cudaStreamNonBlocking);
        cudaEventCreateWithFlags(&evFork, cudaEventDisableTiming);
        cudaEventCreateWithFlags(&evExt,  cudaEventDisableTiming);
    }

    cudaEventRecord(evFork, 0);
    cudaStreamWaitEvent(s2, evFork, 0);

    extract_adj_kernel<<<1000, 256, 0, s2>>>(adj);
    cudaEventRecord(evExt, s2);

    gemm1_tc<<<NN / 64, 128>>>(x, W0, b0);                       // stream 0
    pseudo_fused<<<NN / 4, dim3(64, 4)>>>(W1, b1, y_lab, idx_tr,
                                          out + (size_t)NN * NCLS);
    cudaStreamWaitEvent(0, evExt, 0);
    ew_prop0<<<NN / RPB, 128>>>();
    prop1_final<<<NN / RPB, 128>>>(W2, b2, out);
}

// round 15
// speedup vs baseline: 1.0226x; 1.0004x over previous
#include <cuda_runtime.h>
#include <cuda_bf16.h>
#include <math.h>

// Problem constants
#define NN      8000
#define NFEAT   512
#define NHID    128
#define NCLS    64
#define CAP     96
#define EPS     1e-12f
#define NTRAIN  500
#define RPB     4         // rows per block in prop kernels

#define AST 20            // As smem stride (16 + 4 pad)
#define BST 136           // Bs smem stride (128 + 8 pad)

// ---------------- scratch (device globals; no allocation allowed) ------------
__device__ float g_h     [NN * NHID];
__device__ float g_li0   [NN * NHID];
__device__ float g_yhat  [NN * NCLS];
__device__ int   g_cols  [NN * CAP];
__device__ float g_w     [NN * CAP];
__device__ int   g_deg   [NN];

// ---------------- helpers ----------------------------------------------------
__device__ __forceinline__ unsigned f2tf(float f) {
    unsigned u;
    asm("cvt.rna.tf32.f32 %0, %1;" : "=r"(u) : "f"(f));
    return u;
}

#define MMA_TF32(cc, a, b0_, b1_)                                              \
    asm volatile(                                                              \
        "mma.sync.aligned.m16n8k8.row.col.f32.tf32.tf32.f32 "                  \
        "{%0,%1,%2,%3}, {%4,%5,%6,%7}, {%8,%9}, {%0,%1,%2,%3};"                \
        : "+f"(cc[0]), "+f"(cc[1]), "+f"(cc[2]), "+f"(cc[3])                   \
        : "r"(a[0]), "r"(a[1]), "r"(a[2]), "r"(a[3]), "r"(b0_), "r"(b1_))

// =============================================================================
// KERNEL 1: GEMM1 (tensor tf32-split): h = relu(x @ W0 + b0)   [champion verbatim]
// =============================================================================
__global__ __launch_bounds__(128) void gemm1_tc(const float* __restrict__ x,
                                                const float* __restrict__ W0,
                                                const float* __restrict__ b0) {
    __shared__ unsigned Ah[64 * AST], Al[64 * AST];
    __shared__ unsigned Bh[16 * BST], Bl[16 * BST];

    const int tid  = threadIdx.x;
    const int warp = tid >> 5;
    const int lane = tid & 31;
    const int m0   = blockIdx.x * 64;
    const int wm   = (warp & 1) * 32;
    const int wn   = (warp >> 1) * 64;

    float c[2][8][4];
#pragma unroll
    for (int mt = 0; mt < 2; mt++)
#pragma unroll
        for (int nt = 0; nt < 8; nt++)
#pragma unroll
            for (int r = 0; r < 4; r++) c[mt][nt][r] = 0.0f;

    const int ra = tid >> 1, ca = (tid & 1) * 8;
    const int rb = tid >> 3, cb = (tid & 7) * 16;
    float4 xa[2], wb[4];

    {
        const float* xp = x + (size_t)(m0 + ra) * NFEAT + ca;
        xa[0] = *(const float4*)(xp);
        xa[1] = *(const float4*)(xp + 4);
        const float* wp = W0 + (size_t)rb * NHID + cb;
#pragma unroll
        for (int i = 0; i < 4; i++) wb[i] = *(const float4*)(wp + i * 4);
    }

    for (int it = 0; it < 32; it++) {
        {
            const float* av = (const float*)xa;
#pragma unroll
            for (int j = 0; j < 8; j++) {
                float v  = av[j];
                unsigned hb = f2tf(v);
                Ah[ra * AST + ca + j] = hb;
                Al[ra * AST + ca + j] = f2tf(v - __uint_as_float(hb));
            }
            const float* bv = (const float*)wb;
#pragma unroll
            for (int j = 0; j < 16; j++) {
                float v  = bv[j];
                unsigned hb = f2tf(v);
                Bh[rb * BST + cb + j] = hb;
                Bl[rb * BST + cb + j] = f2tf(v - __uint_as_float(hb));
            }
        }
        __syncthreads();

        if (it < 31) {
            int k0 = (it + 1) * 16;
            const float* xp = x + (size_t)(m0 + ra) * NFEAT + k0 + ca;
            xa[0] = *(const float4*)(xp);
            xa[1] = *(const float4*)(xp + 4);
            const float* wp = W0 + (size_t)(k0 + rb) * NHID + cb;
#pragma unroll
            for (int i = 0; i < 4; i++) wb[i] = *(const float4*)(wp + i * 4);
        }

#pragma unroll
        for (int ks = 0; ks < 16; ks += 8) {
            unsigned ah[2][4], al[2][4];
            const int arow = wm + (lane >> 2);
            const int ac   = ks + (lane & 3);
#pragma unroll
            for (int mt = 0; mt < 2; mt++) {
                int r = arow + mt * 16;
                ah[mt][0] = Ah[r * AST + ac];
                ah[mt][1] = Ah[(r + 8) * AST + ac];
                ah[mt][2] = Ah[r * AST + ac + 4];
                ah[mt][3] = Ah[(r + 8) * AST + ac + 4];
                al[mt][0] = Al[r * AST + ac];
                al[mt][1] = Al[(r + 8) * AST + ac];
                al[mt][2] = Al[r * AST + ac + 4];
                al[mt][3] = Al[(r + 8) * AST + ac + 4];
            }
#pragma unroll
            for (int nt = 0; nt < 8; nt++) {
                const int bn = wn + nt * 8 + (lane >> 2);
                const int bk = ks + (lane & 3);
                unsigned bh0 = Bh[bk * BST + bn];
                unsigned bh1 = Bh[(bk + 4) * BST + bn];
                unsigned bl0 = Bl[bk * BST + bn];
                unsigned bl1 = Bl[(bk + 4) * BST + bn];
#pragma unroll
                for (int mt = 0; mt < 2; mt++) {
                    MMA_TF32(c[mt][nt], ah[mt], bh0, bh1);
                    MMA_TF32(c[mt][nt], ah[mt], bl0, bl1);
                    MMA_TF32(c[mt][nt], al[mt], bh0, bh1);
                }
            }
        }
        __syncthreads();
    }

#pragma unroll
    for (int nt = 0; nt < 8; nt++) {
        int col = wn + nt * 8 + 2 * (lane & 3);
        float bias0 = b0[col], bias1 = b0[col + 1];
#pragma unroll
        for (int mt = 0; mt < 2; mt++) {
            int r = m0 + wm + mt * 16 + (lane >> 2);
            g_h[(size_t)r * NHID + col]           = fmaxf(c[mt][nt][0] + bias0, 0.0f);
            g_h[(size_t)r * NHID + col + 1]       = fmaxf(c[mt][nt][1] + bias1, 0.0f);
            g_h[(size_t)(r + 8) * NHID + col]     = fmaxf(c[mt][nt][2] + bias0, 0.0f);
            g_h[(size_t)(r + 8) * NHID + col + 1] = fmaxf(c[mt][nt][3] + bias1, 0.0f);
        }
    }
}

// =============================================================================
// KERNEL 2: adjacency extraction (1 warp/row)   [champion verbatim]
// =============================================================================
__global__ __launch_bounds__(256) void extract_adj_kernel(const float* __restrict__ adj) {
    int row_id = blockIdx.x * 8 + (threadIdx.x >> 5);
    int lane = threadIdx.x & 31;
    const float* row = adj + (size_t)row_id * NN;
    int base = 0;
    for (int c0 = 0; c0 < 7936; c0 += 128) {
        float4 v = *(const float4*)(row + c0 + lane * 4);
        unsigned m4 = (v.x != 0.0f) | ((v.y != 0.0f) << 1) |
                      ((v.z != 0.0f) << 2) | ((v.w != 0.0f) << 3);
        unsigned act = __ballot_sync(0xffffffffu, m4 != 0);
        if (act == 0) continue;
        int nz = __popc(m4);
        while (act) {
            int l   = __ffs(act) - 1;
            int c_l = __shfl_sync(0xffffffffu, nz, l);
            if (lane == l) {
                int p = base;
                int col = c0 + lane * 4;
                if (m4 & 1) { if (p < CAP) g_cols[row_id * CAP + p] = col;     p++; }
                if (m4 & 2) { if (p < CAP) g_cols[row_id * CAP + p] = col + 1; p++; }
                if (m4 & 4) { if (p < CAP) g_cols[row_id * CAP + p] = col + 2; p++; }
                if (m4 & 8) { if (p < CAP) g_cols[row_id * CAP + p] = col + 3; }
            }
            base += c_l;
            act &= act - 1;
        }
    }
    {
        float2 v = *(const float2*)(row + 7936 + lane * 2);
        unsigned m2 = (v.x != 0.0f) | ((v.y != 0.0f) << 1);
        unsigned act = __ballot_sync(0xffffffffu, m2 != 0);
        int nz = __popc(m2);
        while (act) {
            int l   = __ffs(act) - 1;
            int c_l = __shfl_sync(0xffffffffu, nz, l);
            if (lane == l) {
                int p = base;
                int col = 7936 + lane * 2;
                if (m2 & 1) { if (p < CAP) g_cols[row_id * CAP + p] = col;     p++; }
                if (m2 & 2) { if (p < CAP) g_cols[row_id * CAP + p] = col + 1; }
            }
            base += c_l;
            act &= act - 1;
        }
    }
    if (lane == 0) g_deg[row_id] = base < CAP ? base : CAP;
}

// =============================================================================
// KERNEL 3: Pseudo fused (in-kernel cnt)   [R12 verbatim]
// =============================================================================
__global__ void pseudo_fused(const float* __restrict__ W1,
                             const float* __restrict__ b1,
                             const float* __restrict__ y_label,
                             const int*   __restrict__ idx_tr,
                             float* __restrict__ out_pseudo) {
    int ry = threadIdx.y, c = threadIdx.x;
    int row = blockIdx.x * 4 + ry;
    int tid = ry * 64 + c;
    __shared__ float hr[4][128];
    __shared__ int   idxs[NTRAIN];
    __shared__ float sm[4][2];
    __shared__ int   scnt[4][2];

    hr[ry][c]      = g_h[(size_t)row * NHID + c];
    hr[ry][c + 64] = g_h[(size_t)row * NHID + c + 64];
    for (int i = tid; i < NTRAIN; i += 256) idxs[i] = idx_tr[i];
    __syncthreads();

    float acc = b1[c];
#pragma unroll 8
    for (int k = 0; k < NHID; k++) acc += hr[ry][k] * W1[k * NCLS + c];

    int wu = c >> 5, lane = c & 31;
    int cnt = 0;
    for (int i = c; i < NTRAIN; i += 64) cnt += (idxs[i] == row);
#pragma unroll
    for (int o = 16; o; o >>= 1) cnt += __shfl_xor_sync(0xffffffffu, cnt, o);
    if (lane == 0) scnt[ry][wu] = cnt;
    __syncthreads();
    cnt = scnt[ry][0] + scnt[ry][1];
    if (cnt) acc += 0.1f * (float)cnt * y_label[(size_t)row * NCLS + c];

    out_pseudo[(size_t)row * NCLS + c] = acc;

    float m = acc;
#pragma unroll
    for (int o = 16; o; o >>= 1) m = fmaxf(m, __shfl_xor_sync(0xffffffffu, m, o));
    if (lane == 0) sm[ry][wu] = m;
    __syncthreads();
    m = fmaxf(sm[ry][0], sm[ry][1]);
    __syncthreads();
    float e = expf(acc - m);
    float s = e;
#pragma unroll
    for (int o = 16; o; o >>= 1) s += __shfl_xor_sync(0xffffffffu, s, o);
    if (lane == 0) sm[ry][wu] = s;
    __syncthreads();
    s = sm[ry][0] + sm[ry][1];
    g_yhat[(size_t)row * NCLS + c] = e / s;
}

// =============================================================================
// KERNEL 4: edge weights + propagation layer 0
// [ONLY rewrite this round: warp-per-row float4 SpMM + in-warp norm —
//  barrier-free after the cooperative smem load; ~40% fewer issue slots]
// =============================================================================
__global__ __launch_bounds__(128) void ew_prop0() {
    int row0 = blockIdx.x * RPB;
    __shared__ float yi[RPB][NCLS];
    __shared__ int   cs[RPB][CAP];
    __shared__ float ws[RPB][CAP];
    int t = threadIdx.x;
    int wid = t >> 5, lane = t & 31;
    int row = row0 + wid;

    int degs[RPB];
#pragma unroll
    for (int r = 0; r < RPB; r++) {
        degs[r] = g_deg[row0 + r];
        if (t < degs[r]) cs[r][t] = g_cols[(row0 + r) * CAP + t];
    }
    yi[t >> 6][t & 63]       = g_yhat[(size_t)(row0 + (t >> 6)) * NCLS + (t & 63)];
    yi[2 + (t >> 6)][t & 63] = g_yhat[(size_t)(row0 + 2 + (t >> 6)) * NCLS + (t & 63)];
    __syncthreads();

    const int deg = degs[wid];

    // ---- edge weights: warp `wid` owns row, 2x-unrolled neighbor dots ----
    {
        float my0 = yi[wid][lane], my1 = yi[wid][lane + 32];
        int n = 0;
        for (; n + 2 <= deg; n += 2) {
            const float* yj0 = g_yhat + (size_t)cs[wid][n]     * NCLS;
            const float* yj1 = g_yhat + (size_t)cs[wid][n + 1] * NCLS;
            float p0 = my0 * yj0[lane] + my1 * yj0[lane + 32];
            float p1 = my0 * yj1[lane] + my1 * yj1[lane + 32];
#pragma unroll
            for (int o = 16; o; o >>= 1) {
                p0 += __shfl_down_sync(0xffffffffu, p0, o);
                p1 += __shfl_down_sync(0xffffffffu, p1, o);
            }
            if (lane == 0) { ws[wid][n] = p0; ws[wid][n + 1] = p1; }
        }
        for (; n < deg; n++) {
            const float* yj = g_yhat + (size_t)cs[wid][n] * NCLS;
            float p = my0 * yj[lane] + my1 * yj[lane + 32];
#pragma unroll
            for (int o = 16; o; o >>= 1) p += __shfl_down_sync(0xffffffffu, p, o);
            if (lane == 0) ws[wid][n] = p;
        }
        __syncwarp();
        float s = (lane < deg ? ws[wid][lane] : 0.0f)
                + (lane + 32 < deg ? ws[wid][lane + 32] : 0.0f)
                + (lane + 64 < deg ? ws[wid][lane + 64] : 0.0f);
#pragma unroll
        for (int o = 16; o; o >>= 1) s += __shfl_xor_sync(0xffffffffu, s, o);
        float ssum = fmaxf(s, EPS);
        for (int i = lane; i < deg; i += 32) {
            float wn = ws[wid][i] / ssum;
            ws[wid][i] = wn;
            g_w[row * CAP + i] = wn;
        }
        __syncwarp();
    }

    // ---- SpMM: warp-per-row, lane owns cols 4*lane..4*lane+3 (float4) ----
    float4 a = make_float4(0.f, 0.f, 0.f, 0.f);
    {
        int n = 0;
        for (; n + 4 <= deg; n += 4) {
            float w0 = ws[wid][n], w1 = ws[wid][n + 1];
            float w2 = ws[wid][n + 2], w3 = ws[wid][n + 3];
            float4 h0 = *(const float4*)&g_h[(size_t)cs[wid][n]     * NHID + lane * 4];
            float4 h1 = *(const float4*)&g_h[(size_t)cs[wid][n + 1] * NHID + lane * 4];
            float4 h2 = *(const float4*)&g_h[(size_t)cs[wid][n + 2] * NHID + lane * 4];
            float4 h3 = *(const float4*)&g_h[(size_t)cs[wid][n + 3] * NHID + lane * 4];
            a.x += w0 * h0.x + w1 * h1.x + w2 * h2.x + w3 * h3.x;
            a.y += w0 * h0.y + w1 * h1.y + w2 * h2.y + w3 * h3.y;
            a.z += w0 * h0.z + w1 * h1.z + w2 * h2.z + w3 * h3.z;
            a.w += w0 * h0.w + w1 * h1.w + w2 * h2.w + w3 * h3.w;
        }
        for (; n < deg; n++) {
            float w0 = ws[wid][n];
            float4 h0 = *(const float4*)&g_h[(size_t)cs[wid][n] * NHID + lane * 4];
            a.x += w0 * h0.x; a.y += w0 * h0.y; a.z += w0 * h0.z; a.w += w0 * h0.w;
        }
    }
    float4 hr = *(const float4*)&g_h[(size_t)row * NHID + lane * 4];
    float4 v;
    v.x = 0.9f * a.x + 0.1f * hr.x;
    v.y = 0.9f * a.y + 0.1f * hr.y;
    v.z = 0.9f * a.z + 0.1f * hr.z;
    v.w = 0.9f * a.w + 0.1f * hr.w;

    // in-warp L2 norm (4 squares/lane, 32-lane tree)
    float q = v.x * v.x + v.y * v.y + v.z * v.z + v.w * v.w;
#pragma unroll
    for (int o = 16; o; o >>= 1) q += __shfl_xor_sync(0xffffffffu, q, o);
    float inv = 1.0f / fmaxf(sqrtf(q), EPS);
    float4 outv = make_float4(v.x * inv, v.y * inv, v.z * inv, v.w * inv);
    *(float4*)&g_li0[(size_t)row * NHID + lane * 4] = outv;
}

// =============================================================================
// KERNEL 5: propagation layer 1 + log_softmax (4 rows/block)   [R13 verbatim]
// =============================================================================
__global__ __launch_bounds__(128) void prop1_final(const float* __restrict__ W2,
                                                   const float* __restrict__ b2,
                                                   float* __restrict__ out) {
    int row0 = blockIdx.x * RPB;
    __shared__ int   cs  [RPB][CAP];
    __shared__ float ws  [RPB][CAP];
    __shared__ float li  [RPB][NHID];
    __shared__ float pacc[RPB][NHID];
    __shared__ float w4  [RPB][4];
    __shared__ float smx [RPB][2];
    int t = threadIdx.x;
    int wid = t >> 5, lane = t & 31;

    int degs[RPB];
#pragma unroll
    for (int r = 0; r < RPB; r++) {
        degs[r] = g_deg[row0 + r];
        if (t < degs[r]) {
            cs[r][t] = g_cols[(row0 + r) * CAP + t];
            ws[r][t] = g_w  [(row0 + r) * CAP + t];
        }
    }
    __syncthreads();

    float v[RPB];
#pragma unroll
    for (int r = 0; r < RPB; r++) {
        int deg = degs[r];
        float s = 0.0f;
        int n = 0;
        for (; n + 4 <= deg; n += 4) {
            float a0 = g_li0[(size_t)cs[r][n]     * NHID + t];
            float a1 = g_li0[(size_t)cs[r][n + 1] * NHID + t];
            float a2 = g_li0[(size_t)cs[r][n + 2] * NHID + t];
            float a3 = g_li0[(size_t)cs[r][n + 3] * NHID + t];
            s += ws[r][n] * a0 + ws[r][n + 1] * a1 + ws[r][n + 2] * a2 + ws[r][n + 3] * a3;
        }
        for (; n < deg; n++) s += ws[r][n] * g_li0[(size_t)cs[r][n] * NHID + t];
        v[r] = 0.9f * s + 0.1f * g_h[(size_t)(row0 + r) * NHID + t];
        float q = v[r] * v[r];
#pragma unroll
        for (int o = 16; o; o >>= 1) q += __shfl_xor_sync(0xffffffffu, q, o);
        if (lane == 0) w4[r][wid] = q;
    }
    __syncthreads();
#pragma unroll
    for (int r = 0; r < RPB; r++) {
        float nrm = fmaxf(sqrtf(w4[r][0] + w4[r][1] + w4[r][2] + w4[r][3]), EPS);
        li[r][t] = v[r] / nrm;
    }
    __syncthreads();

    int c = t & 63, ph = t >> 6;
    float acc[RPB] = {0.f, 0.f, 0.f, 0.f};
#pragma unroll 8
    for (int k = ph * 64; k < ph * 64 + 64; k++) {
        float w = W2[k * NCLS + c];
#pragma unroll
        for (int r = 0; r < RPB; r++) acc[r] += li[r][k] * w;
    }
#pragma unroll
    for (int r = 0; r < RPB; r++) pacc[r][t] = acc[r];
    __syncthreads();

    float bias = b2[c];
#pragma unroll
    for (int p = 0; p < 2; p++) {
        int R = (t >> 6) + 2 * p;
        float accv = pacc[R][c] + pacc[R][64 + c] + bias;
        float m = accv;
#pragma unroll
        for (int o = 16; o; o >>= 1) m = fmaxf(m, __shfl_xor_sync(0xffffffffu, m, o));
        if (lane == 0) smx[R][wid & 1] = m;
        __syncthreads();
        m = fmaxf(smx[R][0], smx[R][1]);
        __syncthreads();
        float sh = accv - m;
        float e = expf(sh);
        float ss = e;
#pragma unroll
        for (int o = 16; o; o >>= 1) ss += __shfl_xor_sync(0xffffffffu, ss, o);
        if (lane == 0) smx[R][wid & 1] = ss;
        __syncthreads();
        ss = smx[R][0] + smx[R][1];
        out[(size_t)(row0 + R) * NCLS + c] = sh - logf(ss);
        __syncthreads();
    }
}

// ---------------- launch: 2-stream fork/join --------------------------------
extern "C" void kernel_launch(void* const* d_in, const int* in_sizes, int n_in,
                              void* d_out, int out_size) {
    const float* x      = (const float*)d_in[0];
    const float* adj    = (const float*)d_in[1];
    const float* y_lab  = (const float*)d_in[2];
    const int*   idx_tr = (const int*)  d_in[3];
    const float* W0     = (const float*)d_in[4];
    const float* b0     = (const float*)d_in[5];
    const float* W1     = (const float*)d_in[6];
    const float* b1     = (const float*)d_in[7];
    const float* W2     = (const float*)d_in[8];
    const float* b2     = (const float*)d_in[9];
    float* out = (float*)d_out;

    static cudaStream_t s2 = nullptr;
    static cudaEvent_t evFork = nullptr, evExt = nullptr;
    if (s2 == nullptr) {
        cudaStreamCreateWithFlags(&s2, cudaStreamNonBlocking);
        cudaEventCreateWithFlags(&evFork, cudaEventDisableTiming);
        cudaEventCreateWithFlags(&evExt,  cudaEventDisableTiming);
    }

    cudaEventRecord(evFork, 0);
    cudaStreamWaitEvent(s2, evFork, 0);

    extract_adj_kernel<<<1000, 256, 0, s2>>>(adj);
    cudaEventRecord(evExt, s2);

    gemm1_tc<<<NN / 64, 128>>>(x, W0, b0);                       // stream 0
    pseudo_fused<<<NN / 4, dim3(64, 4)>>>(W1, b1, y_lab, idx_tr,
                                          out + (size_t)NN * NCLS);
    cudaStreamWaitEvent(0, evExt, 0);
    ew_prop0<<<NN / RPB, 128>>>();
    prop1_final<<<NN / RPB, 128>>>(W2, b2, out);
}

// round 16
// speedup vs baseline: 1.0267x; 1.0040x over previous
#include <cuda_runtime.h>
#include <cuda_bf16.h>
#include <math.h>

// Problem constants
#define NN      8000
#define NFEAT   512
#define NHID    128
#define NCLS    64
#define CAP     96
#define EPS     1e-12f
#define NTRAIN  500
#define RPB     4         // rows per block in prop kernels

#define AST 20            // As smem stride (16 + 4 pad)
#define BST 136           // Bs smem stride (128 + 8 pad)

// ---------------- scratch (device globals; no allocation allowed) ------------
__device__ float g_h     [NN * NHID];
__device__ float g_li0   [NN * NHID];
__device__ float g_yhat  [NN * NCLS];
__device__ int   g_cols  [NN * CAP];
__device__ float g_w     [NN * CAP];
__device__ int   g_deg   [NN];

// ---------------- helpers ----------------------------------------------------
__device__ __forceinline__ unsigned f2tf(float f) {
    unsigned u;
    asm("cvt.rna.tf32.f32 %0, %1;" : "=r"(u) : "f"(f));
    return u;
}

#define MMA_TF32(cc, a, b0_, b1_)                                              \
    asm volatile(                                                              \
        "mma.sync.aligned.m16n8k8.row.col.f32.tf32.tf32.f32 "                  \
        "{%0,%1,%2,%3}, {%4,%5,%6,%7}, {%8,%9}, {%0,%1,%2,%3};"                \
        : "+f"(cc[0]), "+f"(cc[1]), "+f"(cc[2]), "+f"(cc[3])                   \
        : "r"(a[0]), "r"(a[1]), "r"(a[2]), "r"(a[3]), "r"(b0_), "r"(b1_))

// =============================================================================
// KERNEL 1: GEMM1 (tensor tf32-split): h = relu(x @ W0 + b0)   [champion verbatim]
// =============================================================================
__global__ __launch_bounds__(128) void gemm1_tc(const float* __restrict__ x,
                                                const float* __restrict__ W0,
                                                const float* __restrict__ b0) {
    __shared__ unsigned Ah[64 * AST], Al[64 * AST];
    __shared__ unsigned Bh[16 * BST], Bl[16 * BST];

    const int tid  = threadIdx.x;
    const int warp = tid >> 5;
    const int lane = tid & 31;
    const int m0   = blockIdx.x * 64;
    const int wm   = (warp & 1) * 32;
    const int wn   = (warp >> 1) * 64;

    float c[2][8][4];
#pragma unroll
    for (int mt = 0; mt < 2; mt++)
#pragma unroll
        for (int nt = 0; nt < 8; nt++)
#pragma unroll
            for (int r = 0; r < 4; r++) c[mt][nt][r] = 0.0f;

    const int ra = tid >> 1, ca = (tid & 1) * 8;
    const int rb = tid >> 3, cb = (tid & 7) * 16;
    float4 xa[2], wb[4];

    {
        const float* xp = x + (size_t)(m0 + ra) * NFEAT + ca;
        xa[0] = *(const float4*)(xp);
        xa[1] = *(const float4*)(xp + 4);
        const float* wp = W0 + (size_t)rb * NHID + cb;
#pragma unroll
        for (int i = 0; i < 4; i++) wb[i] = *(const float4*)(wp + i * 4);
    }

    for (int it = 0; it < 32; it++) {
        {
            const float* av = (const float*)xa;
#pragma unroll
            for (int j = 0; j < 8; j++) {
                float v  = av[j];
                unsigned hb = f2tf(v);
                Ah[ra * AST + ca + j] = hb;
                Al[ra * AST + ca + j] = f2tf(v - __uint_as_float(hb));
            }
            const float* bv = (const float*)wb;
#pragma unroll
            for (int j = 0; j < 16; j++) {
                float v  = bv[j];
                unsigned hb = f2tf(v);
                Bh[rb * BST + cb + j] = hb;
                Bl[rb * BST + cb + j] = f2tf(v - __uint_as_float(hb));
            }
        }
        __syncthreads();

        if (it < 31) {
            int k0 = (it + 1) * 16;
            const float* xp = x + (size_t)(m0 + ra) * NFEAT + k0 + ca;
            xa[0] = *(const float4*)(xp);
            xa[1] = *(const float4*)(xp + 4);
            const float* wp = W0 + (size_t)(k0 + rb) * NHID + cb;
#pragma unroll
            for (int i = 0; i < 4; i++) wb[i] = *(const float4*)(wp + i * 4);
        }

#pragma unroll
        for (int ks = 0; ks < 16; ks += 8) {
            unsigned ah[2][4], al[2][4];
            const int arow = wm + (lane >> 2);
            const int ac   = ks + (lane & 3);
#pragma unroll
            for (int mt = 0; mt < 2; mt++) {
                int r = arow + mt * 16;
                ah[mt][0] = Ah[r * AST + ac];
                ah[mt][1] = Ah[(r + 8) * AST + ac];
                ah[mt][2] = Ah[r * AST + ac + 4];
                ah[mt][3] = Ah[(r + 8) * AST + ac + 4];
                al[mt][0] = Al[r * AST + ac];
                al[mt][1] = Al[(r + 8) * AST + ac];
                al[mt][2] = Al[r * AST + ac + 4];
                al[mt][3] = Al[(r + 8) * AST + ac + 4];
            }
#pragma unroll
            for (int nt = 0; nt < 8; nt++) {
                const int bn = wn + nt * 8 + (lane >> 2);
                const int bk = ks + (lane & 3);
                unsigned bh0 = Bh[bk * BST + bn];
                unsigned bh1 = Bh[(bk + 4) * BST + bn];
                unsigned bl0 = Bl[bk * BST + bn];
                unsigned bl1 = Bl[(bk + 4) * BST + bn];
#pragma unroll
                for (int mt = 0; mt < 2; mt++) {
                    MMA_TF32(c[mt][nt], ah[mt], bh0, bh1);
                    MMA_TF32(c[mt][nt], ah[mt], bl0, bl1);
                    MMA_TF32(c[mt][nt], al[mt], bh0, bh1);
                }
            }
        }
        __syncthreads();
    }

#pragma unroll
    for (int nt = 0; nt < 8; nt++) {
        int col = wn + nt * 8 + 2 * (lane & 3);
        float bias0 = b0[col], bias1 = b0[col + 1];
#pragma unroll
        for (int mt = 0; mt < 2; mt++) {
            int r = m0 + wm + mt * 16 + (lane >> 2);
            g_h[(size_t)r * NHID + col]           = fmaxf(c[mt][nt][0] + bias0, 0.0f);
            g_h[(size_t)r * NHID + col + 1]       = fmaxf(c[mt][nt][1] + bias1, 0.0f);
            g_h[(size_t)(r + 8) * NHID + col]     = fmaxf(c[mt][nt][2] + bias0, 0.0f);
            g_h[(size_t)(r + 8) * NHID + col + 1] = fmaxf(c[mt][nt][3] + bias1, 0.0f);
        }
    }
}

// =============================================================================
// KERNEL 2: adjacency extraction (1 warp/row)   [champion verbatim]
// =============================================================================
__global__ __launch_bounds__(256) void extract_adj_kernel(const float* __restrict__ adj) {
    int row_id = blockIdx.x * 8 + (threadIdx.x >> 5);
    int lane = threadIdx.x & 31;
    const float* row = adj + (size_t)row_id * NN;
    int base = 0;
    for (int c0 = 0; c0 < 7936; c0 += 128) {
        float4 v = *(const float4*)(row + c0 + lane * 4);
        unsigned m4 = (v.x != 0.0f) | ((v.y != 0.0f) << 1) |
                      ((v.z != 0.0f) << 2) | ((v.w != 0.0f) << 3);
        unsigned act = __ballot_sync(0xffffffffu, m4 != 0);
        if (act == 0) continue;
        int nz = __popc(m4);
        while (act) {
            int l   = __ffs(act) - 1;
            int c_l = __shfl_sync(0xffffffffu, nz, l);
            if (lane == l) {
                int p = base;
                int col = c0 + lane * 4;
                if (m4 & 1) { if (p < CAP) g_cols[row_id * CAP + p] = col;     p++; }
                if (m4 & 2) { if (p < CAP) g_cols[row_id * CAP + p] = col + 1; p++; }
                if (m4 & 4) { if (p < CAP) g_cols[row_id * CAP + p] = col + 2; p++; }
                if (m4 & 8) { if (p < CAP) g_cols[row_id * CAP + p] = col + 3; }
            }
            base += c_l;
            act &= act - 1;
        }
    }
    {
        float2 v = *(const float2*)(row + 7936 + lane * 2);
        unsigned m2 = (v.x != 0.0f) | ((v.y != 0.0f) << 1);
        unsigned act = __ballot_sync(0xffffffffu, m2 != 0);
        int nz = __popc(m2);
        while (act) {
            int l   = __ffs(act) - 1;
            int c_l = __shfl_sync(0xffffffffu, nz, l);
            if (lane == l) {
                int p = base;
                int col = 7936 + lane * 2;
                if (m2 & 1) { if (p < CAP) g_cols[row_id * CAP + p] = col;     p++; }
                if (m2 & 2) { if (p < CAP) g_cols[row_id * CAP + p] = col + 1; }
            }
            base += c_l;
            act &= act - 1;
        }
    }
    if (lane == 0) g_deg[row_id] = base < CAP ? base : CAP;
}

// =============================================================================
// KERNEL 3: Pseudo fused (in-kernel cnt)   [R12 verbatim]
// =============================================================================
__global__ void pseudo_fused(const float* __restrict__ W1,
                             const float* __restrict__ b1,
                             const float* __restrict__ y_label,
                             const int*   __restrict__ idx_tr,
                             float* __restrict__ out_pseudo) {
    int ry = threadIdx.y, c = threadIdx.x;
    int row = blockIdx.x * 4 + ry;
    int tid = ry * 64 + c;
    __shared__ float hr[4][128];
    __shared__ int   idxs[NTRAIN];
    __shared__ float sm[4][2];
    __shared__ int   scnt[4][2];

    hr[ry][c]      = g_h[(size_t)row * NHID + c];
    hr[ry][c + 64] = g_h[(size_t)row * NHID + c + 64];
    for (int i = tid; i < NTRAIN; i += 256) idxs[i] = idx_tr[i];
    __syncthreads();

    float acc = b1[c];
#pragma unroll 8
    for (int k = 0; k < NHID; k++) acc += hr[ry][k] * W1[k * NCLS + c];

    int wu = c >> 5, lane = c & 31;
    int cnt = 0;
    for (int i = c; i < NTRAIN; i += 64) cnt += (idxs[i] == row);
#pragma unroll
    for (int o = 16; o; o >>= 1) cnt += __shfl_xor_sync(0xffffffffu, cnt, o);
    if (lane == 0) scnt[ry][wu] = cnt;
    __syncthreads();
    cnt = scnt[ry][0] + scnt[ry][1];
    if (cnt) acc += 0.1f * (float)cnt * y_label[(size_t)row * NCLS + c];

    out_pseudo[(size_t)row * NCLS + c] = acc;

    float m = acc;
#pragma unroll
    for (int o = 16; o; o >>= 1) m = fmaxf(m, __shfl_xor_sync(0xffffffffu, m, o));
    if (lane == 0) sm[ry][wu] = m;
    __syncthreads();
    m = fmaxf(sm[ry][0], sm[ry][1]);
    __syncthreads();
    float e = expf(acc - m);
    float s = e;
#pragma unroll
    for (int o = 16; o; o >>= 1) s += __shfl_xor_sync(0xffffffffu, s, o);
    if (lane == 0) sm[ry][wu] = s;
    __syncthreads();
    s = sm[ry][0] + sm[ry][1];
    g_yhat[(size_t)row * NCLS + c] = e / s;
}

// =============================================================================
// KERNEL 4: edge weights + propagation layer 0   [R15 verbatim]
// =============================================================================
__global__ __launch_bounds__(128) void ew_prop0() {
    int row0 = blockIdx.x * RPB;
    __shared__ float yi[RPB][NCLS];
    __shared__ int   cs[RPB][CAP];
    __shared__ float ws[RPB][CAP];
    int t = threadIdx.x;
    int wid = t >> 5, lane = t & 31;
    int row = row0 + wid;

    int degs[RPB];
#pragma unroll
    for (int r = 0; r < RPB; r++) {
        degs[r] = g_deg[row0 + r];
        if (t < degs[r]) cs[r][t] = g_cols[(row0 + r) * CAP + t];
    }
    yi[t >> 6][t & 63]       = g_yhat[(size_t)(row0 + (t >> 6)) * NCLS + (t & 63)];
    yi[2 + (t >> 6)][t & 63] = g_yhat[(size_t)(row0 + 2 + (t >> 6)) * NCLS + (t & 63)];
    __syncthreads();

    const int deg = degs[wid];

    {
        float my0 = yi[wid][lane], my1 = yi[wid][lane + 32];
        int n = 0;
        for (; n + 2 <= deg; n += 2) {
            const float* yj0 = g_yhat + (size_t)cs[wid][n]     * NCLS;
            const float* yj1 = g_yhat + (size_t)cs[wid][n + 1] * NCLS;
            float p0 = my0 * yj0[lane] + my1 * yj0[lane + 32];
            float p1 = my0 * yj1[lane] + my1 * yj1[lane + 32];
#pragma unroll
            for (int o = 16; o; o >>= 1) {
                p0 += __shfl_down_sync(0xffffffffu, p0, o);
                p1 += __shfl_down_sync(0xffffffffu, p1, o);
            }
            if (lane == 0) { ws[wid][n] = p0; ws[wid][n + 1] = p1; }
        }
        for (; n < deg; n++) {
            const float* yj = g_yhat + (size_t)cs[wid][n] * NCLS;
            float p = my0 * yj[lane] + my1 * yj[lane + 32];
#pragma unroll
            for (int o = 16; o; o >>= 1) p += __shfl_down_sync(0xffffffffu, p, o);
            if (lane == 0) ws[wid][n] = p;
        }
        __syncwarp();
        float s = (lane < deg ? ws[wid][lane] : 0.0f)
                + (lane + 32 < deg ? ws[wid][lane + 32] : 0.0f)
                + (lane + 64 < deg ? ws[wid][lane + 64] : 0.0f);
#pragma unroll
        for (int o = 16; o; o >>= 1) s += __shfl_xor_sync(0xffffffffu, s, o);
        float ssum = fmaxf(s, EPS);
        for (int i = lane; i < deg; i += 32) {
            float wn = ws[wid][i] / ssum;
            ws[wid][i] = wn;
            g_w[row * CAP + i] = wn;
        }
        __syncwarp();
    }

    float4 a = make_float4(0.f, 0.f, 0.f, 0.f);
    {
        int n = 0;
        for (; n + 4 <= deg; n += 4) {
            float w0 = ws[wid][n], w1 = ws[wid][n + 1];
            float w2 = ws[wid][n + 2], w3 = ws[wid][n + 3];
            float4 h0 = *(const float4*)&g_h[(size_t)cs[wid][n]     * NHID + lane * 4];
            float4 h1 = *(const float4*)&g_h[(size_t)cs[wid][n + 1] * NHID + lane * 4];
            float4 h2 = *(const float4*)&g_h[(size_t)cs[wid][n + 2] * NHID + lane * 4];
            float4 h3 = *(const float4*)&g_h[(size_t)cs[wid][n + 3] * NHID + lane * 4];
            a.x += w0 * h0.x + w1 * h1.x + w2 * h2.x + w3 * h3.x;
            a.y += w0 * h0.y + w1 * h1.y + w2 * h2.y + w3 * h3.y;
            a.z += w0 * h0.z + w1 * h1.z + w2 * h2.z + w3 * h3.z;
            a.w += w0 * h0.w + w1 * h1.w + w2 * h2.w + w3 * h3.w;
        }
        for (; n < deg; n++) {
            float w0 = ws[wid][n];
            float4 h0 = *(const float4*)&g_h[(size_t)cs[wid][n] * NHID + lane * 4];
            a.x += w0 * h0.x; a.y += w0 * h0.y; a.z += w0 * h0.z; a.w += w0 * h0.w;
        }
    }
    float4 hr = *(const float4*)&g_h[(size_t)row * NHID + lane * 4];
    float4 v;
    v.x = 0.9f * a.x + 0.1f * hr.x;
    v.y = 0.9f * a.y + 0.1f * hr.y;
    v.z = 0.9f * a.z + 0.1f * hr.z;
    v.w = 0.9f * a.w + 0.1f * hr.w;

    float q = v.x * v.x + v.y * v.y + v.z * v.z + v.w * v.w;
#pragma unroll
    for (int o = 16; o; o >>= 1) q += __shfl_xor_sync(0xffffffffu, q, o);
    float inv = 1.0f / fmaxf(sqrtf(q), EPS);
    float4 outv = make_float4(v.x * inv, v.y * inv, v.z * inv, v.w * inv);
    *(float4*)&g_li0[(size_t)row * NHID + lane * 4] = outv;
}

// =============================================================================
// KERNEL 5: propagation layer 1 + log_softmax (4 rows/block)
// [ONLY rewrite this round: warp-per-row float4 SpMM + in-warp norm
//  (mirrors the measured ew_prop0 win); W2 GEMV + softmax epilogue unchanged]
// =============================================================================
__global__ __launch_bounds__(128) void prop1_final(const float* __restrict__ W2,
                                                   const float* __restrict__ b2,
                                                   float* __restrict__ out) {
    int row0 = blockIdx.x * RPB;
    __shared__ int   cs  [RPB][CAP];
    __shared__ float ws  [RPB][CAP];
    __shared__ float li  [RPB][NHID];
    __shared__ float pacc[RPB][NHID];
    __shared__ float smx [RPB][2];
    int t = threadIdx.x;
    int wid = t >> 5, lane = t & 31;
    int row = row0 + wid;

    int degs[RPB];
#pragma unroll
    for (int r = 0; r < RPB; r++) {
        degs[r] = g_deg[row0 + r];
        if (t < degs[r]) {
            cs[r][t] = g_cols[(row0 + r) * CAP + t];
            ws[r][t] = g_w  [(row0 + r) * CAP + t];
        }
    }
    __syncthreads();

    // ---- SpMM: warp-per-row, lane owns cols 4*lane..4*lane+3 (float4) ----
    const int deg = degs[wid];
    float4 a = make_float4(0.f, 0.f, 0.f, 0.f);
    {
        int n = 0;
        for (; n + 4 <= deg; n += 4) {
            float w0 = ws[wid][n], w1 = ws[wid][n + 1];
            float w2 = ws[wid][n + 2], w3 = ws[wid][n + 3];
            float4 h0 = *(const float4*)&g_li0[(size_t)cs[wid][n]     * NHID + lane * 4];
            float4 h1 = *(const float4*)&g_li0[(size_t)cs[wid][n + 1] * NHID + lane * 4];
            float4 h2 = *(const float4*)&g_li0[(size_t)cs[wid][n + 2] * NHID + lane * 4];
            float4 h3 = *(const float4*)&g_li0[(size_t)cs[wid][n + 3] * NHID + lane * 4];
            a.x += w0 * h0.x + w1 * h1.x + w2 * h2.x + w3 * h3.x;
            a.y += w0 * h0.y + w1 * h1.y + w2 * h2.y + w3 * h3.y;
            a.z += w0 * h0.z + w1 * h1.z + w2 * h2.z + w3 * h3.z;
            a.w += w0 * h0.w + w1 * h1.w + w2 * h2.w + w3 * h3.w;
        }
        for (; n < deg; n++) {
            float w0 = ws[wid][n];
            float4 h0 = *(const float4*)&g_li0[(size_t)cs[wid][n] * NHID + lane * 4];
            a.x += w0 * h0.x; a.y += w0 * h0.y; a.z += w0 * h0.z; a.w += w0 * h0.w;
        }
    }
    float4 hr = *(const float4*)&g_h[(size_t)row * NHID + lane * 4];
    float4 v;
    v.x = 0.9f * a.x + 0.1f * hr.x;
    v.y = 0.9f * a.y + 0.1f * hr.y;
    v.z = 0.9f * a.z + 0.1f * hr.z;
    v.w = 0.9f * a.w + 0.1f * hr.w;

    float q = v.x * v.x + v.y * v.y + v.z * v.z + v.w * v.w;
#pragma unroll
    for (int o = 16; o; o >>= 1) q += __shfl_xor_sync(0xffffffffu, q, o);
    float inv = 1.0f / fmaxf(sqrtf(q), EPS);
    *(float4*)&li[wid][lane * 4] = make_float4(v.x * inv, v.y * inv,
                                               v.z * inv, v.w * inv);
    __syncthreads();

    // ---- shared-W2 GEMV: 4 rows per W2 load ----
    int c = t & 63, ph = t >> 6;
    float acc[RPB] = {0.f, 0.f, 0.f, 0.f};
#pragma unroll 8
    for (int k = ph * 64; k < ph * 64 + 64; k++) {
        float w = W2[k * NCLS + c];
#pragma unroll
        for (int r = 0; r < RPB; r++) acc[r] += li[r][k] * w;
    }
#pragma unroll
    for (int r = 0; r < RPB; r++) pacc[r][t] = acc[r];
    __syncthreads();

    // ---- log_softmax epilogue ----
    float bias = b2[c];
#pragma unroll
    for (int p = 0; p < 2; p++) {
        int R = (t >> 6) + 2 * p;
        float accv = pacc[R][c] + pacc[R][64 + c] + bias;
        float m = accv;
#pragma unroll
        for (int o = 16; o; o >>= 1) m = fmaxf(m, __shfl_xor_sync(0xffffffffu, m, o));
        if (lane == 0) smx[R][wid & 1] = m;
        __syncthreads();
        m = fmaxf(smx[R][0], smx[R][1]);
        __syncthreads();
        float sh = accv - m;
        float e = expf(sh);
        float ss = e;
#pragma unroll
        for (int o = 16; o; o >>= 1) ss += __shfl_xor_sync(0xffffffffu, ss, o);
        if (lane == 0) smx[R][wid & 1] = ss;
        __syncthreads();
        ss = smx[R][0] + smx[R][1];
        out[(size_t)(row0 + R) * NCLS + c] = sh - logf(ss);
        __syncthreads();
    }
}

// ---------------- launch: 2-stream fork/join --------------------------------
extern "C" void kernel_launch(void* const* d_in, const int* in_sizes, int n_in,
                              void* d_out, int out_size) {
    const float* x      = (const float*)d_in[0];
    const float* adj    = (const float*)d_in[1];
    const float* y_lab  = (const float*)d_in[2];
    const int*   idx_tr = (const int*)  d_in[3];
    const float* W0     = (const float*)d_in[4];
    const float* b0     = (const float*)d_in[5];
    const float* W1     = (const float*)d_in[6];
    const float* b1     = (const float*)d_in[7];
    const float* W2     = (const float*)d_in[8];
    const float* b2     = (const float*)d_in[9];
    float* out = (float*)d_out;

    static cudaStream_t s2 = nullptr;
    static cudaEvent_t evFork = nullptr, evExt = nullptr;
    if (s2 == nullptr) {
        cudaStreamCreateWithFlags(&s2, cudaStreamNonBlocking);
        cudaEventCreateWithFlags(&evFork, cudaEventDisableTiming);
        cudaEventCreateWithFlags(&evExt,  cudaEventDisableTiming);
    }

    cudaEventRecord(evFork, 0);
    cudaStreamWaitEvent(s2, evFork, 0);

    extract_adj_kernel<<<1000, 256, 0, s2>>>(adj);
    cudaEventRecord(evExt, s2);

    gemm1_tc<<<NN / 64, 128>>>(x, W0, b0);                       // stream 0
    pseudo_fused<<<NN / 4, dim3(64, 4)>>>(W1, b1, y_lab, idx_tr,
                                          out + (size_t)NN * NCLS);
    cudaStreamWaitEvent(0, evExt, 0);
    ew_prop0<<<NN / RPB, 128>>>();
    prop1_final<<<NN / RPB, 128>>>(W2, b2, out);
}

// round 17
// speedup vs baseline: 1.0487x; 1.0215x over previous
#include <cuda_runtime.h>
#include <cuda_bf16.h>
#include <math.h>

// Problem constants
#define NN      8000
#define NFEAT   512
#define NHID    128
#define NCLS    64
#define CAP     96
#define EPS     1e-12f
#define NTRAIN  500
#define RPB     4         // rows per block in prop kernels

#define AST 20            // As smem stride (16 + 4 pad)
#define BST 136           // Bs smem stride (128 + 8 pad)

// ---------------- scratch (device globals; no allocation allowed) ------------
__device__ float g_h     [NN * NHID];
__device__ float g_li0   [NN * NHID];
__device__ float g_yhat  [NN * NCLS];
__device__ int   g_cols  [NN * CAP];
__device__ float g_w     [NN * CAP];
__device__ int   g_deg   [NN];

// ---------------- helpers ----------------------------------------------------
__device__ __forceinline__ unsigned f2tf(float f) {
    unsigned u;
    asm("cvt.rna.tf32.f32 %0, %1;" : "=r"(u) : "f"(f));
    return u;
}

#define MMA_TF32(cc, a, b0_, b1_)                                              \
    asm volatile(                                                              \
        "mma.sync.aligned.m16n8k8.row.col.f32.tf32.tf32.f32 "                  \
        "{%0,%1,%2,%3}, {%4,%5,%6,%7}, {%8,%9}, {%0,%1,%2,%3};"                \
        : "+f"(cc[0]), "+f"(cc[1]), "+f"(cc[2]), "+f"(cc[3])                   \
        : "r"(a[0]), "r"(a[1]), "r"(a[2]), "r"(a[3]), "r"(b0_), "r"(b1_))

// =============================================================================
// KERNEL 1: GEMM1 (tensor tf32-split): h = relu(x @ W0 + b0)   [champion verbatim]
// =============================================================================
__global__ __launch_bounds__(128) void gemm1_tc(const float* __restrict__ x,
                                                const float* __restrict__ W0,
                                                const float* __restrict__ b0) {
    __shared__ unsigned Ah[64 * AST], Al[64 * AST];
    __shared__ unsigned Bh[16 * BST], Bl[16 * BST];

    const int tid  = threadIdx.x;
    const int warp = tid >> 5;
    const int lane = tid & 31;
    const int m0   = blockIdx.x * 64;
    const int wm   = (warp & 1) * 32;
    const int wn   = (warp >> 1) * 64;

    float c[2][8][4];
#pragma unroll
    for (int mt = 0; mt < 2; mt++)
#pragma unroll
        for (int nt = 0; nt < 8; nt++)
#pragma unroll
            for (int r = 0; r < 4; r++) c[mt][nt][r] = 0.0f;

    const int ra = tid >> 1, ca = (tid & 1) * 8;
    const int rb = tid >> 3, cb = (tid & 7) * 16;
    float4 xa[2], wb[4];

    {
        const float* xp = x + (size_t)(m0 + ra) * NFEAT + ca;
        xa[0] = *(const float4*)(xp);
        xa[1] = *(const float4*)(xp + 4);
        const float* wp = W0 + (size_t)rb * NHID + cb;
#pragma unroll
        for (int i = 0; i < 4; i++) wb[i] = *(const float4*)(wp + i * 4);
    }

    for (int it = 0; it < 32; it++) {
        {
            const float* av = (const float*)xa;
#pragma unroll
            for (int j = 0; j < 8; j++) {
                float v  = av[j];
                unsigned hb = f2tf(v);
                Ah[ra * AST + ca + j] = hb;
                Al[ra * AST + ca + j] = f2tf(v - __uint_as_float(hb));
            }
            const float* bv = (const float*)wb;
#pragma unroll
            for (int j = 0; j < 16; j++) {
                float v  = bv[j];
                unsigned hb = f2tf(v);
                Bh[rb * BST + cb + j] = hb;
                Bl[rb * BST + cb + j] = f2tf(v - __uint_as_float(hb));
            }
        }
        __syncthreads();

        if (it < 31) {
            int k0 = (it + 1) * 16;
            const float* xp = x + (size_t)(m0 + ra) * NFEAT + k0 + ca;
            xa[0] = *(const float4*)(xp);
            xa[1] = *(const float4*)(xp + 4);
            const float* wp = W0 + (size_t)(k0 + rb) * NHID + cb;
#pragma unroll
            for (int i = 0; i < 4; i++) wb[i] = *(const float4*)(wp + i * 4);
        }

#pragma unroll
        for (int ks = 0; ks < 16; ks += 8) {
            unsigned ah[2][4], al[2][4];
            const int arow = wm + (lane >> 2);
            const int ac   = ks + (lane & 3);
#pragma unroll
            for (int mt = 0; mt < 2; mt++) {
                int r = arow + mt * 16;
                ah[mt][0] = Ah[r * AST + ac];
                ah[mt][1] = Ah[(r + 8) * AST + ac];
                ah[mt][2] = Ah[r * AST + ac + 4];
                ah[mt][3] = Ah[(r + 8) * AST + ac + 4];
                al[mt][0] = Al[r * AST + ac];
                al[mt][1] = Al[(r + 8) * AST + ac];
                al[mt][2] = Al[r * AST + ac + 4];
                al[mt][3] = Al[(r + 8) * AST + ac + 4];
            }
#pragma unroll
            for (int nt = 0; nt < 8; nt++) {
                const int bn = wn + nt * 8 + (lane >> 2);
                const int bk = ks + (lane & 3);
                unsigned bh0 = Bh[bk * BST + bn];
                unsigned bh1 = Bh[(bk + 4) * BST + bn];
                unsigned bl0 = Bl[bk * BST + bn];
                unsigned bl1 = Bl[(bk + 4) * BST + bn];
#pragma unroll
                for (int mt = 0; mt < 2; mt++) {
                    MMA_TF32(c[mt][nt], ah[mt], bh0, bh1);
                    MMA_TF32(c[mt][nt], ah[mt], bl0, bl1);
                    MMA_TF32(c[mt][nt], al[mt], bh0, bh1);
                }
            }
        }
        __syncthreads();
    }

#pragma unroll
    for (int nt = 0; nt < 8; nt++) {
        int col = wn + nt * 8 + 2 * (lane & 3);
        float bias0 = b0[col], bias1 = b0[col + 1];
#pragma unroll
        for (int mt = 0; mt < 2; mt++) {
            int r = m0 + wm + mt * 16 + (lane >> 2);
            g_h[(size_t)r * NHID + col]           = fmaxf(c[mt][nt][0] + bias0, 0.0f);
            g_h[(size_t)r * NHID + col + 1]       = fmaxf(c[mt][nt][1] + bias1, 0.0f);
            g_h[(size_t)(r + 8) * NHID + col]     = fmaxf(c[mt][nt][2] + bias0, 0.0f);
            g_h[(size_t)(r + 8) * NHID + col + 1] = fmaxf(c[mt][nt][3] + bias1, 0.0f);
        }
    }
}

// =============================================================================
// KERNEL 2: adjacency extraction (1 warp/row)   [champion verbatim]
// =============================================================================
__global__ __launch_bounds__(256) void extract_adj_kernel(const float* __restrict__ adj) {
    int row_id = blockIdx.x * 8 + (threadIdx.x >> 5);
    int lane = threadIdx.x & 31;
    const float* row = adj + (size_t)row_id * NN;
    int base = 0;
    for (int c0 = 0; c0 < 7936; c0 += 128) {
        float4 v = *(const float4*)(row + c0 + lane * 4);
        unsigned m4 = (v.x != 0.0f) | ((v.y != 0.0f) << 1) |
                      ((v.z != 0.0f) << 2) | ((v.w != 0.0f) << 3);
        unsigned act = __ballot_sync(0xffffffffu, m4 != 0);
        if (act == 0) continue;
        int nz = __popc(m4);
        while (act) {
            int l   = __ffs(act) - 1;
            int c_l = __shfl_sync(0xffffffffu, nz, l);
            if (lane == l) {
                int p = base;
                int col = c0 + lane * 4;
                if (m4 & 1) { if (p < CAP) g_cols[row_id * CAP + p] = col;     p++; }
                if (m4 & 2) { if (p < CAP) g_cols[row_id * CAP + p] = col + 1; p++; }
                if (m4 & 4) { if (p < CAP) g_cols[row_id * CAP + p] = col + 2; p++; }
                if (m4 & 8) { if (p < CAP) g_cols[row_id * CAP + p] = col + 3; }
            }
            base += c_l;
            act &= act - 1;
        }
    }
    {
        float2 v = *(const float2*)(row + 7936 + lane * 2);
        unsigned m2 = (v.x != 0.0f) | ((v.y != 0.0f) << 1);
        unsigned act = __ballot_sync(0xffffffffu, m2 != 0);
        int nz = __popc(m2);
        while (act) {
            int l   = __ffs(act) - 1;
            int c_l = __shfl_sync(0xffffffffu, nz, l);
            if (lane == l) {
                int p = base;
                int col = 7936 + lane * 2;
                if (m2 & 1) { if (p < CAP) g_cols[row_id * CAP + p] = col;     p++; }
                if (m2 & 2) { if (p < CAP) g_cols[row_id * CAP + p] = col + 1; }
            }
            base += c_l;
            act &= act - 1;
        }
    }
    if (lane == 0) g_deg[row_id] = base < CAP ? base : CAP;
}

// =============================================================================
// KERNEL 3: Pseudo fused (in-kernel cnt)   [R12 verbatim]
// =============================================================================
__global__ void pseudo_fused(const float* __restrict__ W1,
                             const float* __restrict__ b1,
                             const float* __restrict__ y_label,
                             const int*   __restrict__ idx_tr,
                             float* __restrict__ out_pseudo) {
    int ry = threadIdx.y, c = threadIdx.x;
    int row = blockIdx.x * 4 + ry;
    int tid = ry * 64 + c;
    __shared__ float hr[4][128];
    __shared__ int   idxs[NTRAIN];
    __shared__ float sm[4][2];
    __shared__ int   scnt[4][2];

    hr[ry][c]      = g_h[(size_t)row * NHID + c];
    hr[ry][c + 64] = g_h[(size_t)row * NHID + c + 64];
    for (int i = tid; i < NTRAIN; i += 256) idxs[i] = idx_tr[i];
    __syncthreads();

    float acc = b1[c];
#pragma unroll 8
    for (int k = 0; k < NHID; k++) acc += hr[ry][k] * W1[k * NCLS + c];

    int wu = c >> 5, lane = c & 31;
    int cnt = 0;
    for (int i = c; i < NTRAIN; i += 64) cnt += (idxs[i] == row);
#pragma unroll
    for (int o = 16; o; o >>= 1) cnt += __shfl_xor_sync(0xffffffffu, cnt, o);
    if (lane == 0) scnt[ry][wu] = cnt;
    __syncthreads();
    cnt = scnt[ry][0] + scnt[ry][1];
    if (cnt) acc += 0.1f * (float)cnt * y_label[(size_t)row * NCLS + c];

    out_pseudo[(size_t)row * NCLS + c] = acc;

    float m = acc;
#pragma unroll
    for (int o = 16; o; o >>= 1) m = fmaxf(m, __shfl_xor_sync(0xffffffffu, m, o));
    if (lane == 0) sm[ry][wu] = m;
    __syncthreads();
    m = fmaxf(sm[ry][0], sm[ry][1]);
    __syncthreads();
    float e = expf(acc - m);
    float s = e;
#pragma unroll
    for (int o = 16; o; o >>= 1) s += __shfl_xor_sync(0xffffffffu, s, o);
    if (lane == 0) sm[ry][wu] = s;
    __syncthreads();
    s = sm[ry][0] + sm[ry][1];
    g_yhat[(size_t)row * NCLS + c] = e / s;
}

// =============================================================================
// KERNEL 4: edge weights + propagation layer 0
// [ONLY change this round: weight phase = 4 neighbors x 8 lanes, float4 dots,
//  width-8 shuffle reduce — ~3x fewer issue slots than the 2x-unrolled version]
// =============================================================================
__global__ __launch_bounds__(128) void ew_prop0() {
    int row0 = blockIdx.x * RPB;
    __shared__ float yi[RPB][NCLS];
    __shared__ int   cs[RPB][CAP];
    __shared__ float ws[RPB][CAP];
    int t = threadIdx.x;
    int wid = t >> 5, lane = t & 31;
    int row = row0 + wid;

    int degs[RPB];
#pragma unroll
    for (int r = 0; r < RPB; r++) {
        degs[r] = g_deg[row0 + r];
        if (t < degs[r]) cs[r][t] = g_cols[(row0 + r) * CAP + t];
    }
    yi[t >> 6][t & 63]       = g_yhat[(size_t)(row0 + (t >> 6)) * NCLS + (t & 63)];
    yi[2 + (t >> 6)][t & 63] = g_yhat[(size_t)(row0 + 2 + (t >> 6)) * NCLS + (t & 63)];
    __syncthreads();

    const int deg = degs[wid];

    // ---- edge weights: 4 neighbors in parallel, 8 lanes per neighbor ----
    {
        const int sub = lane >> 3;        // neighbor slot 0..3
        const int el  = lane & 7;         // float4 element group 0..7
        const float4* yi4 = (const float4*)&yi[wid][0];
        float4 ya = yi4[el], yb = yi4[el + 8];
        for (int n = 0; n < deg; n += 4) {
            int nn = n + sub;
            float p = 0.0f;
            if (nn < deg) {
                const float4* yj4 = (const float4*)(g_yhat + (size_t)cs[wid][nn] * NCLS);
                float4 ja = yj4[el], jb = yj4[el + 8];
                p = ya.x * ja.x + ya.y * ja.y + ya.z * ja.z + ya.w * ja.w
                  + yb.x * jb.x + yb.y * jb.y + yb.z * jb.z + yb.w * jb.w;
            }
            p += __shfl_xor_sync(0xffffffffu, p, 4);
            p += __shfl_xor_sync(0xffffffffu, p, 2);
            p += __shfl_xor_sync(0xffffffffu, p, 1);
            if (el == 0 && nn < deg) ws[wid][nn] = p;
        }
        __syncwarp();
        float s = (lane < deg ? ws[wid][lane] : 0.0f)
                + (lane + 32 < deg ? ws[wid][lane + 32] : 0.0f)
                + (lane + 64 < deg ? ws[wid][lane + 64] : 0.0f);
#pragma unroll
        for (int o = 16; o; o >>= 1) s += __shfl_xor_sync(0xffffffffu, s, o);
        float ssum = fmaxf(s, EPS);
        for (int i = lane; i < deg; i += 32) {
            float wn = ws[wid][i] / ssum;
            ws[wid][i] = wn;
            g_w[row * CAP + i] = wn;
        }
        __syncwarp();
    }

    // ---- SpMM: warp-per-row, lane owns cols 4*lane..4*lane+3 (float4) ----
    float4 a = make_float4(0.f, 0.f, 0.f, 0.f);
    {
        int n = 0;
        for (; n + 4 <= deg; n += 4) {
            float w0 = ws[wid][n], w1 = ws[wid][n + 1];
            float w2 = ws[wid][n + 2], w3 = ws[wid][n + 3];
            float4 h0 = *(const float4*)&g_h[(size_t)cs[wid][n]     * NHID + lane * 4];
            float4 h1 = *(const float4*)&g_h[(size_t)cs[wid][n + 1] * NHID + lane * 4];
            float4 h2 = *(const float4*)&g_h[(size_t)cs[wid][n + 2] * NHID + lane * 4];
            float4 h3 = *(const float4*)&g_h[(size_t)cs[wid][n + 3] * NHID + lane * 4];
            a.x += w0 * h0.x + w1 * h1.x + w2 * h2.x + w3 * h3.x;
            a.y += w0 * h0.y + w1 * h1.y + w2 * h2.y + w3 * h3.y;
            a.z += w0 * h0.z + w1 * h1.z + w2 * h2.z + w3 * h3.z;
            a.w += w0 * h0.w + w1 * h1.w + w2 * h2.w + w3 * h3.w;
        }
        for (; n < deg; n++) {
            float w0 = ws[wid][n];
            float4 h0 = *(const float4*)&g_h[(size_t)cs[wid][n] * NHID + lane * 4];
            a.x += w0 * h0.x; a.y += w0 * h0.y; a.z += w0 * h0.z; a.w += w0 * h0.w;
        }
    }
    float4 hr = *(const float4*)&g_h[(size_t)row * NHID + lane * 4];
    float4 v;
    v.x = 0.9f * a.x + 0.1f * hr.x;
    v.y = 0.9f * a.y + 0.1f * hr.y;
    v.z = 0.9f * a.z + 0.1f * hr.z;
    v.w = 0.9f * a.w + 0.1f * hr.w;

    float q = v.x * v.x + v.y * v.y + v.z * v.z + v.w * v.w;
#pragma unroll
    for (int o = 16; o; o >>= 1) q += __shfl_xor_sync(0xffffffffu, q, o);
    float inv = 1.0f / fmaxf(sqrtf(q), EPS);
    float4 outv = make_float4(v.x * inv, v.y * inv, v.z * inv, v.w * inv);
    *(float4*)&g_li0[(size_t)row * NHID + lane * 4] = outv;
}

// =============================================================================
// KERNEL 5: propagation layer 1 + log_softmax (4 rows/block)   [R16 verbatim]
// =============================================================================
__global__ __launch_bounds__(128) void prop1_final(const float* __restrict__ W2,
                                                   const float* __restrict__ b2,
                                                   float* __restrict__ out) {
    int row0 = blockIdx.x * RPB;
    __shared__ int   cs  [RPB][CAP];
    __shared__ float ws  [RPB][CAP];
    __shared__ float li  [RPB][NHID];
    __shared__ float pacc[RPB][NHID];
    __shared__ float smx [RPB][2];
    int t = threadIdx.x;
    int wid = t >> 5, lane = t & 31;
    int row = row0 + wid;

    int degs[RPB];
#pragma unroll
    for (int r = 0; r < RPB; r++) {
        degs[r] = g_deg[row0 + r];
        if (t < degs[r]) {
            cs[r][t] = g_cols[(row0 + r) * CAP + t];
            ws[r][t] = g_w  [(row0 + r) * CAP + t];
        }
    }
    __syncthreads();

    const int deg = degs[wid];
    float4 a = make_float4(0.f, 0.f, 0.f, 0.f);
    {
        int n = 0;
        for (; n + 4 <= deg; n += 4) {
            float w0 = ws[wid][n], w1 = ws[wid][n + 1];
            float w2 = ws[wid][n + 2], w3 = ws[wid][n + 3];
            float4 h0 = *(const float4*)&g_li0[(size_t)cs[wid][n]     * NHID + lane * 4];
            float4 h1 = *(const float4*)&g_li0[(size_t)cs[wid][n + 1] * NHID + lane * 4];
            float4 h2 = *(const float4*)&g_li0[(size_t)cs[wid][n + 2] * NHID + lane * 4];
            float4 h3 = *(const float4*)&g_li0[(size_t)cs[wid][n + 3] * NHID + lane * 4];
            a.x += w0 * h0.x + w1 * h1.x + w2 * h2.x + w3 * h3.x;
            a.y += w0 * h0.y + w1 * h1.y + w2 * h2.y + w3 * h3.y;
            a.z += w0 * h0.z + w1 * h1.z + w2 * h2.z + w3 * h3.z;
            a.w += w0 * h0.w + w1 * h1.w + w2 * h2.w + w3 * h3.w;
        }
        for (; n < deg; n++) {
            float w0 = ws[wid][n];
            float4 h0 = *(const float4*)&g_li0[(size_t)cs[wid][n] * NHID + lane * 4];
            a.x += w0 * h0.x; a.y += w0 * h0.y; a.z += w0 * h0.z; a.w += w0 * h0.w;
        }
    }
    float4 hr = *(const float4*)&g_h[(size_t)row * NHID + lane * 4];
    float4 v;
    v.x = 0.9f * a.x + 0.1f * hr.x;
    v.y = 0.9f * a.y + 0.1f * hr.y;
    v.z = 0.9f * a.z + 0.1f * hr.z;
    v.w = 0.9f * a.w + 0.1f * hr.w;

    float q = v.x * v.x + v.y * v.y + v.z * v.z + v.w * v.w;
#pragma unroll
    for (int o = 16; o; o >>= 1) q += __shfl_xor_sync(0xffffffffu, q, o);
    float inv = 1.0f / fmaxf(sqrtf(q), EPS);
    *(float4*)&li[wid][lane * 4] = make_float4(v.x * inv, v.y * inv,
                                               v.z * inv, v.w * inv);
    __syncthreads();

    int c = t & 63, ph = t >> 6;
    float acc[RPB] = {0.f, 0.f, 0.f, 0.f};
#pragma unroll 8
    for (int k = ph * 64; k < ph * 64 + 64; k++) {
        float w = W2[k * NCLS + c];
#pragma unroll
        for (int r = 0; r < RPB; r++) acc[r] += li[r][k] * w;
    }
#pragma unroll
    for (int r = 0; r < RPB; r++) pacc[r][t] = acc[r];
    __syncthreads();

    float bias = b2[c];
#pragma unroll
    for (int p = 0; p < 2; p++) {
        int R = (t >> 6) + 2 * p;
        float accv = pacc[R][c] + pacc[R][64 + c] + bias;
        float m = accv;
#pragma unroll
        for (int o = 16; o; o >>= 1) m = fmaxf(m, __shfl_xor_sync(0xffffffffu, m, o));
        if (lane == 0) smx[R][wid & 1] = m;
        __syncthreads();
        m = fmaxf(smx[R][0], smx[R][1]);
        __syncthreads();
        float sh = accv - m;
        float e = expf(sh);
        float ss = e;
#pragma unroll
        for (int o = 16; o; o >>= 1) ss += __shfl_xor_sync(0xffffffffu, ss, o);
        if (lane == 0) smx[R][wid & 1] = ss;
        __syncthreads();
        ss = smx[R][0] + smx[R][1];
        out[(size_t)(row0 + R) * NCLS + c] = sh - logf(ss);
        __syncthreads();
    }
}

// ---------------- launch: 2-stream fork/join --------------------------------
extern "C" void kernel_launch(void* const* d_in, const int* in_sizes, int n_in,
                              void* d_out, int out_size) {
    const float* x      = (const float*)d_in[0];
    const float* adj    = (const float*)d_in[1];
    const float* y_lab  = (const float*)d_in[2];
    const int*   idx_tr = (const int*)  d_in[3];
    const float* W0     = (const float*)d_in[4];
    const float* b0     = (const float*)d_in[5];
    const float* W1     = (const float*)d_in[6];
    const float* b1     = (const float*)d_in[7];
    const float* W2     = (const float*)d_in[8];
    const float* b2     = (const float*)d_in[9];
    float* out = (float*)d_out;

    static cudaStream_t s2 = nullptr;
    static cudaEvent_t evFork = nullptr, evExt = nullptr;
    if (s2 == nullptr) {
        cudaStreamCreateWithFlags(&s2, cudaStreamNonBlocking);
        cudaEventCreateWithFlags(&evFork, cudaEventDisableTiming);
        cudaEventCreateWithFlags(&evExt,  cudaEventDisableTiming);
    }

    cudaEventRecord(evFork, 0);
    cudaStreamWaitEvent(s2, evFork, 0);

    extract_adj_kernel<<<1000, 256, 0, s2>>>(adj);
    cudaEventRecord(evExt, s2);

    gemm1_tc<<<NN / 64, 128>>>(x, W0, b0);                       // stream 0
    pseudo_fused<<<NN / 4, dim3(64, 4)>>>(W1, b1, y_lab, idx_tr,
                                          out + (size_t)NN * NCLS);
    cudaStreamWaitEvent(0, evExt, 0);
    ew_prop0<<<NN / RPB, 128>>>();
    prop1_final<<<NN / RPB, 128>>>(W2, b2, out);
}